// round 1
// baseline (speedup 1.0000x reference)
#include <cuda_runtime.h>
#include <math.h>

// ---------------- problem constants ----------------
#define BATCH 16384
#define HID   256
#define LK    4

// output layout (flat float32 concat of the reference tuple)
#define OFF_HNEXT 0
#define OFF_GS    (BATCH * HID)                       // 4194304
#define OFF_GNODE (OFF_GS + 9)                        // 4194313
#define OFF_MARG  (OFF_GNODE + BATCH * 9 * HID)       // 41943049
#define GROW      (9 * HID)                           // 2304, G_node row stride

// ---------------- scratch (device globals; no allocation allowed) --------
__device__ float g_hL[BATCH * 1024];    // h @ [L0|L1|L2|L3]
__device__ float g_tmp[BATCH * 1024];
__device__ float g_cand[BATCH * 1024];
__device__ float g_rows[6 * 4 * BATCH]; // per-row scores, [stage][k][b]

// ---------------- epilogue modes ----------------
#define EPI_NONE 0
#define EPI_SIG  1
#define EPI_ADD  2   // acc + D + bias
#define EPI_MUL  3   // acc * D + bias
#define EPI_OMZ  4   // 1 - (acc + bias)

// ---------------- generic tiled SGEMM ----------------
// C[r, n] = epilogue( A1 @ W1 (+ A2 @ W2) ), weights are the (4,256,256)
// tensors addressed as concatenated 256x(4*256): col n -> slice n>>8, col n&255.
#define BM 128
#define BN 128
#define BKK 8
#define TM 8
#define TN 8

__global__ __launch_bounds__(256, 2)
void gemm_kernel(const float* __restrict__ A1, int lda1,
                 const float* __restrict__ W1,
                 const float* __restrict__ A2, int lda2,
                 const float* __restrict__ W2,
                 int K1, int K2,
                 const float* __restrict__ bias,
                 const float* __restrict__ D, int ldd,
                 float* __restrict__ C, int ldc,
                 int mode)
{
    __shared__ float As[BKK][BM];
    __shared__ float Bs[BKK][BN];

    const int bx = blockIdx.x, by = blockIdx.y;
    const int tid = threadIdx.x;
    const int tx = tid & 15, ty = tid >> 4;

    const int row0 = by * BM;
    const int n0   = bx * BN;
    const int kslice = n0 >> 8;
    const int wc0    = n0 & 255;
    const float* W1b = W1 + kslice * (HID * HID) + wc0;
    const float* W2b = W2 ? (W2 + kslice * (HID * HID) + wc0) : (const float*)0;

    float acc[TM][TN];
#pragma unroll
    for (int i = 0; i < TM; i++)
#pragma unroll
        for (int j = 0; j < TN; j++) acc[i][j] = 0.f;

    const int KT = K1 + K2;
    for (int kt = 0; kt < KT; kt += BKK) {
        const float* A; int lda; const float* Wb; int kk0;
        if (kt < K1) { A = A1; lda = lda1; Wb = W1b; kk0 = kt; }
        else         { A = A2; lda = lda2; Wb = W2b; kk0 = kt - K1; }

        // load A tile (BM x BKK) -> As[kk][m]
#pragma unroll
        for (int i = 0; i < 4; i++) {
            int idx = tid * 4 + i;           // 0..1023
            int m  = idx >> 3;
            int kk = idx & 7;
            As[kk][m] = A[(row0 + m) * lda + kk0 + kk];
        }
        // load W tile (BKK x BN) -> Bs[kk][n]
#pragma unroll
        for (int i = 0; i < 4; i++) {
            int idx = tid * 4 + i;
            int n  = idx & 127;
            int kk = idx >> 7;
            Bs[kk][n] = Wb[(kk0 + kk) * HID + n];
        }
        __syncthreads();

#pragma unroll
        for (int kk = 0; kk < BKK; kk++) {
            float a[TM], w[TN];
            const float4* a4 = reinterpret_cast<const float4*>(&As[kk][ty * TM]);
            const float4* w4 = reinterpret_cast<const float4*>(&Bs[kk][tx * TN]);
            float4 av0 = a4[0], av1 = a4[1];
            float4 wv0 = w4[0], wv1 = w4[1];
            a[0]=av0.x; a[1]=av0.y; a[2]=av0.z; a[3]=av0.w;
            a[4]=av1.x; a[5]=av1.y; a[6]=av1.z; a[7]=av1.w;
            w[0]=wv0.x; w[1]=wv0.y; w[2]=wv0.z; w[3]=wv0.w;
            w[4]=wv1.x; w[5]=wv1.y; w[6]=wv1.z; w[7]=wv1.w;
#pragma unroll
            for (int i = 0; i < TM; i++)
#pragma unroll
                for (int j = 0; j < TN; j++)
                    acc[i][j] += a[i] * w[j];
        }
        __syncthreads();
    }

    // epilogue
    const int gn0 = n0 + tx * TN;
#pragma unroll
    for (int i = 0; i < TM; i++) {
        const int r = row0 + ty * TM + i;
#pragma unroll
        for (int j = 0; j < TN; j++) {
            const int n = gn0 + j;
            const float bv = bias ? bias[n] : 0.f;
            float v = acc[i][j];
            float res;
            if (mode == EPI_SIG) {
                v += bv;
                res = 1.f / (1.f + expf(-v));
            } else if (mode == EPI_ADD) {
                res = v + D[r * ldd + n] + bv;
            } else if (mode == EPI_MUL) {
                res = v * D[r * ldd + n] + bv;
            } else if (mode == EPI_OMZ) {
                res = 1.f - (v + bv);
            } else {
                res = v + bv;
            }
            C[r * ldc + n] = res;
        }
    }
}

// ---------------- mixture kernel: one block (256 thr) per batch row -------
__global__ __launch_bounds__(256)
void mixture_kernel(const float* __restrict__ cand,   // [BATCH, 1024]
                    const float* __restrict__ Ws,
                    float* __restrict__ out1, int ldo1,
                    float* __restrict__ out2,         // optional, stride 256
                    float* __restrict__ rowscores)    // [4][BATCH]
{
    const int b = blockIdx.x;
    const int d = threadIdx.x;
    const int lane = d & 31, warp = d >> 5;

    const float* cr = cand + b * 1024;
    const float c0 = cr[d];
    const float c1 = cr[256 + d];
    const float c2 = cr[512 + d];
    const float c3 = cr[768 + d];
    const float wv = Ws[d];

    float s0 = c0 * wv, s1 = c1 * wv, s2 = c2 * wv, s3 = c3 * wv;
#pragma unroll
    for (int o = 16; o > 0; o >>= 1) {
        s0 += __shfl_down_sync(0xffffffffu, s0, o);
        s1 += __shfl_down_sync(0xffffffffu, s1, o);
        s2 += __shfl_down_sync(0xffffffffu, s2, o);
        s3 += __shfl_down_sync(0xffffffffu, s3, o);
    }
    __shared__ float red[8][4];
    __shared__ float sc[4];
    if (lane == 0) { red[warp][0]=s0; red[warp][1]=s1; red[warp][2]=s2; red[warp][3]=s3; }
    __syncthreads();
    if (d < 4) {
        float t = 0.f;
#pragma unroll
        for (int w = 0; w < 8; w++) t += red[w][d];
        sc[d] = t;
        rowscores[d * BATCH + b] = t;
    }
    __syncthreads();

    const float a0 = sc[0], a1 = sc[1], a2 = sc[2], a3 = sc[3];
    const float mx = fmaxf(fmaxf(a0, a1), fmaxf(a2, a3));
    const float e0 = expf(a0 - mx), e1 = expf(a1 - mx);
    const float e2 = expf(a2 - mx), e3 = expf(a3 - mx);
    const float inv = 1.f / (e0 + e1 + e2 + e3);
    const float o = (e0 * c0 + e1 * c1 + e2 * c2 + e3 * c3) * inv;

    out1[b * ldo1 + d] = o;
    if (out2) out2[b * HID + d] = o;
}

// ---------------- z2 = z1 copy ----------------
__global__ void copy_z2_kernel(float* __restrict__ out)
{
    const int b = blockIdx.x;
    const int d = threadIdx.x;
    out[OFF_GNODE + (b * 9 + 2) * HID + d] = out[OFF_GNODE + (b * 9 + 0) * HID + d];
}

// ---------------- finalize: score sums -> idx/margins ----------------
__global__ __launch_bounds__(256)
void finalize_kernel(const float* __restrict__ rs, float* __restrict__ out)
{
    __shared__ double tmp[256];
    __shared__ double ssum[24];
    const int tid = threadIdx.x;

    for (int idx = 0; idx < 24; idx++) {
        double p = 0.0;
        for (int i = tid; i < BATCH; i += 256) p += (double)rs[idx * BATCH + i];
        tmp[tid] = p;
        __syncthreads();
        for (int o = 128; o > 0; o >>= 1) {
            if (tid < o) tmp[tid] += tmp[tid + o];
            __syncthreads();
        }
        if (tid == 0) ssum[idx] = tmp[0];
        __syncthreads();
    }

    if (tid == 0) {
        out[OFF_GS + 0] = 0.f;
        out[OFF_GS + 1] = 1.f;
        out[OFF_GS + 2] = 0.f;
        for (int s = 0; s < 6; s++) {
            double best = ssum[s * 4]; int bi = 0;
            for (int k = 1; k < 4; k++)
                if (ssum[s * 4 + k] > best) { best = ssum[s * 4 + k]; bi = k; }
            double second = -1e300;
            for (int k = 0; k < 4; k++)
                if (k != bi && ssum[s * 4 + k] > second) second = ssum[s * 4 + k];
            out[OFF_GS + 3 + s] = (float)bi;
            out[OFF_MARG + s]   = (float)(best - second);
        }
    }
}

// ---------------- launcher ----------------
extern "C" void kernel_launch(void* const* d_in, const int* in_sizes, int n_in,
                              void* d_out, int out_size)
{
    const float* x  = (const float*)d_in[0];
    const float* h  = (const float*)d_in[1];
    const float* L  = (const float*)d_in[2];
    const float* R  = (const float*)d_in[3];
    const float* bb = (const float*)d_in[4];   // (4,256) flat = concat bias
    const float* Ws = (const float*)d_in[5];
    float* out = (float*)d_out;

    float *p_hL, *p_tmp, *p_cand, *p_rows;
    cudaGetSymbolAddress((void**)&p_hL,   g_hL);
    cudaGetSymbolAddress((void**)&p_tmp,  g_tmp);
    cudaGetSymbolAddress((void**)&p_cand, g_cand);
    cudaGetSymbolAddress((void**)&p_rows, g_rows);

    float* gnode = out + OFF_GNODE;
    const dim3 blk(256);
    const dim3 g512(512 / BN, BATCH / BM);
    const dim3 g1024(1024 / BN, BATCH / BM);

    // ---- stage 0: z1 = sig(x@L0 + h@R0 + b0); r = sig(x@L1 + h@R1 + b1)
    gemm_kernel<<<g512, blk>>>(x, HID, L, h, HID, R, HID, HID,
                               bb, (const float*)0, 0,
                               gnode, GROW, EPI_SIG);
    // z2 = z1
    copy_z2_kernel<<<BATCH, blk>>>(out);

    // ---- hL = h @ [L0..L3]  (reused by stages A and E)
    gemm_kernel<<<g1024, blk>>>(h, HID, L, (const float*)0, 0, (const float*)0,
                                HID, 0, (const float*)0, (const float*)0, 0,
                                p_hL, 1024, EPI_NONE);

    // ---- stage A: cand = h@L + r@R + b ; rh -> slot 3
    gemm_kernel<<<g1024, blk>>>(gnode + 1 * HID, GROW, R,
                                (const float*)0, 0, (const float*)0,
                                HID, 0, bb, p_hL, 1024,
                                p_cand, 1024, EPI_ADD);
    mixture_kernel<<<BATCH, blk>>>(p_cand, Ws, gnode + 3 * HID, GROW,
                                   (float*)0, p_rows + 0 * 4 * BATCH);

    // ---- stage B: cand = x@L + rh@R + b ; h_tilde -> slot 4
    gemm_kernel<<<g1024, blk>>>(x, HID, L, gnode + 3 * HID, GROW, R,
                                HID, HID, bb, (const float*)0, 0,
                                p_cand, 1024, EPI_NONE);
    mixture_kernel<<<BATCH, blk>>>(p_cand, Ws, gnode + 4 * HID, GROW,
                                   (float*)0, p_rows + 1 * 4 * BATCH);

    // ---- stage C: cand = 1 - (z1@R + b) ; oneMinusZ1 -> slot 5
    gemm_kernel<<<g1024, blk>>>(gnode + 0 * HID, GROW, R,
                                (const float*)0, 0, (const float*)0,
                                HID, 0, bb, (const float*)0, 0,
                                p_cand, 1024, EPI_OMZ);
    mixture_kernel<<<BATCH, blk>>>(p_cand, Ws, gnode + 5 * HID, GROW,
                                   (float*)0, p_rows + 2 * 4 * BATCH);

    // ---- stage D: cand = (h_tilde@L) * (oneMinusZ1@R) + b ; zh_tilde -> slot 6
    gemm_kernel<<<g1024, blk>>>(gnode + 4 * HID, GROW, L,
                                (const float*)0, 0, (const float*)0,
                                HID, 0, (const float*)0, (const float*)0, 0,
                                p_tmp, 1024, EPI_NONE);
    gemm_kernel<<<g1024, blk>>>(gnode + 5 * HID, GROW, R,
                                (const float*)0, 0, (const float*)0,
                                HID, 0, bb, p_tmp, 1024,
                                p_cand, 1024, EPI_MUL);
    mixture_kernel<<<BATCH, blk>>>(p_cand, Ws, gnode + 6 * HID, GROW,
                                   (float*)0, p_rows + 3 * 4 * BATCH);

    // ---- stage E: cand = (h@L) * (z2@R) + b ; z2h -> slot 7
    gemm_kernel<<<g1024, blk>>>(gnode + 2 * HID, GROW, R,
                                (const float*)0, 0, (const float*)0,
                                HID, 0, bb, p_hL, 1024,
                                p_cand, 1024, EPI_MUL);
    mixture_kernel<<<BATCH, blk>>>(p_cand, Ws, gnode + 7 * HID, GROW,
                                   (float*)0, p_rows + 4 * 4 * BATCH);

    // ---- stage F: cand = zh_tilde@L + z2h@R + b ; h_next -> slot 8 + h_next out
    gemm_kernel<<<g1024, blk>>>(gnode + 6 * HID, GROW, L,
                                gnode + 7 * HID, GROW, R,
                                HID, HID, bb, (const float*)0, 0,
                                p_cand, 1024, EPI_NONE);
    mixture_kernel<<<BATCH, blk>>>(p_cand, Ws, gnode + 8 * HID, GROW,
                                   out + OFF_HNEXT, p_rows + 5 * 4 * BATCH);

    // ---- structure + margins
    finalize_kernel<<<1, blk>>>(p_rows, out);
}

// round 4
// speedup vs baseline: 2.5238x; 2.5238x over previous
#include <cuda_runtime.h>
#include <cuda_bf16.h>
#include <math.h>
#include <stdint.h>

// ---------------- problem constants ----------------
#define BATCH 16384
#define HID   256

// output layout (flat float32 concat of the reference tuple)
#define OFF_HNEXT 0
#define OFF_GS    (BATCH * HID)
#define OFF_GNODE (OFF_GS + 9)
#define OFF_MARG  (OFF_GNODE + BATCH * 9 * HID)
#define GROW      (9 * HID)

// ---------------- epilogue modes ----------------
#define EPI_NONE 0
#define EPI_SIG  1
#define EPI_ADD  2   // acc + D + bias
#define EPI_MUL  3   // acc * D + bias
#define EPI_OMZ  4   // 1 - (acc + bias)

// ---------------- scratch (device globals) ----------------
__device__ float g_hL[BATCH * 1024];
__device__ float g_tmp[BATCH * 1024];
__device__ float g_cand[BATCH * 1024];
__device__ float g_rows[6 * 4 * BATCH];

#define UNIT (BATCH * HID)
__device__ __nv_bfloat16 g_bf[18ull * UNIT];
#define WUNIT (4 * 256 * 256)
__device__ __nv_bfloat16 g_w[4 * WUNIT];

// ---------------- helpers ----------------
__device__ __forceinline__ uint32_t smem_u32(const void* p) {
    uint32_t a;
    asm("{ .reg .u64 t; cvta.to.shared.u64 t, %1; cvt.u32.u64 %0, t; }" : "=r"(a) : "l"(p));
    return a;
}

#define CP16(saddr, gaddr) \
    asm volatile("cp.async.ca.shared.global [%0], [%1], 16;" :: "r"(saddr), "l"(gaddr))
#define CP_COMMIT() asm volatile("cp.async.commit_group;")
#define CP_WAIT1()  asm volatile("cp.async.wait_group 1;")
#define CP_WAIT0()  asm volatile("cp.async.wait_group 0;")

__device__ __forceinline__ void ldm_x4(uint32_t* r, uint32_t addr) {
    asm volatile("ldmatrix.sync.aligned.m8n8.x4.shared.b16 {%0,%1,%2,%3}, [%4];"
                 : "=r"(r[0]), "=r"(r[1]), "=r"(r[2]), "=r"(r[3]) : "r"(addr));
}
__device__ __forceinline__ void ldm_x2(uint32_t* r, uint32_t addr) {
    asm volatile("ldmatrix.sync.aligned.m8n8.x2.shared.b16 {%0,%1}, [%2];"
                 : "=r"(r[0]), "=r"(r[1]) : "r"(addr));
}
__device__ __forceinline__ void mma_bf16(float* d, const uint32_t* a, const uint32_t* b) {
    asm volatile(
        "mma.sync.aligned.m16n8k16.row.col.f32.bf16.bf16.f32 "
        "{%0,%1,%2,%3}, {%4,%5,%6,%7}, {%8,%9}, {%0,%1,%2,%3};"
        : "+f"(d[0]), "+f"(d[1]), "+f"(d[2]), "+f"(d[3])
        : "r"(a[0]), "r"(a[1]), "r"(a[2]), "r"(a[3]), "r"(b[0]), "r"(b[1]));
}

// ---------------- HMMA GEMM ----------------
// C[16384, N] = epi( sum_p A_p(bf16 hi/lo) @ W_p(bf16 hi/lo, K-major [d][h]) )
// stage layout (bf16 elems, LDS = 40): Ah | Al | Bh | Bl, each 128*40
#define LDS 40
#define TILE_E (128 * LDS)                 // 5120 elems
#define STAGE_E (4 * TILE_E)               // 20480 elems
#define DYN_SMEM (2 * STAGE_E * 2)         // 81920 bytes

__global__ __launch_bounds__(256, 2)
void tc_gemm(const __nv_bfloat16* __restrict__ A1h, const __nv_bfloat16* __restrict__ A1l, int lda1,
             const __nv_bfloat16* __restrict__ W1h, const __nv_bfloat16* __restrict__ W1l,
             const __nv_bfloat16* __restrict__ A2h, const __nv_bfloat16* __restrict__ A2l, int lda2,
             const __nv_bfloat16* __restrict__ W2h, const __nv_bfloat16* __restrict__ W2l,
             int nPair,
             const float* __restrict__ bias,
             const float* __restrict__ Dop, int ldd,
             float* __restrict__ C, int ldc,
             __nv_bfloat16* __restrict__ Obh, __nv_bfloat16* __restrict__ Obl, int ldob,
             int mode)
{
    extern __shared__ __nv_bfloat16 sm[];
    const int tid  = threadIdx.x;
    const int wid  = tid >> 5;
    const int lane = tid & 31;

    const int row0   = blockIdx.y * 128;
    const int n0     = blockIdx.x * 128;
    const int kslice = n0 >> 8;
    const int wc0    = n0 & 255;

    const __nv_bfloat16* wBh1 = W1h + kslice * 65536;
    const __nv_bfloat16* wBl1 = W1l + kslice * 65536;
    const __nv_bfloat16* wBh2 = W2h ? W2h + kslice * 65536 : (const __nv_bfloat16*)0;
    const __nv_bfloat16* wBl2 = W2l ? W2l + kslice * 65536 : (const __nv_bfloat16*)0;

    const uint32_t smb = smem_u32(sm);
    const int NCH = nPair * 8;

    // per-thread load mapping: row = tid>>1, koff = (tid&1)*16 (elems), 2x16B each tile
    const int lrow = tid >> 1;
    const int lkof = (tid & 1) * 16;

    float acc[64];
#pragma unroll
    for (int i = 0; i < 64; i++) acc[i] = 0.f;

    const int wm = (wid >> 2) * 64;
    const int wn = (wid & 3) * 32;

    // ---- chunk loader (cp.async) ----
    auto load_chunk = [&](int c, int buf) {
        const __nv_bfloat16 *pAh, *pAl, *pWh, *pWl;
        int lda;
        if (c < 8) { pAh = A1h; pAl = A1l; lda = lda1; pWh = wBh1; pWl = wBl1; }
        else       { pAh = A2h; pAl = A2l; lda = lda2; pWh = wBh2; pWl = wBl2; }
        const int k0 = (c & 7) * 32;
        const uint32_t sb = smb + buf * STAGE_E * 2;
        const uint32_t so = (lrow * LDS + lkof) * 2;
        const __nv_bfloat16* gA = pAh + (size_t)(row0 + lrow) * lda + k0 + lkof;
        CP16(sb + so,      gA);
        CP16(sb + so + 16, gA + 8);
        const __nv_bfloat16* gAl = pAl + (size_t)(row0 + lrow) * lda + k0 + lkof;
        CP16(sb + TILE_E * 2 + so,      gAl);
        CP16(sb + TILE_E * 2 + so + 16, gAl + 8);
        const __nv_bfloat16* gW = pWh + (size_t)(wc0 + lrow) * 256 + k0 + lkof;
        CP16(sb + TILE_E * 4 + so,      gW);
        CP16(sb + TILE_E * 4 + so + 16, gW + 8);
        const __nv_bfloat16* gWl = pWl + (size_t)(wc0 + lrow) * 256 + k0 + lkof;
        CP16(sb + TILE_E * 6 + so,      gWl);
        CP16(sb + TILE_E * 6 + so + 16, gWl + 8);
        CP_COMMIT();
    };

    load_chunk(0, 0);

    for (int c = 0; c < NCH; c++) {
        if (c + 1 < NCH) {
            load_chunk(c + 1, (c + 1) & 1);
            CP_WAIT1();
        } else {
            CP_WAIT0();
        }
        __syncthreads();

        const uint32_t sb = smb + (c & 1) * STAGE_E * 2;
        const uint32_t aRow = (uint32_t)(wm + (lane & 15));
        const uint32_t aKh  = (uint32_t)((lane >> 4) * 8);
        const uint32_t bRow = (uint32_t)(wn + (lane & 7));
        const uint32_t bKh  = (uint32_t)(((lane >> 3) & 1) * 8);

#pragma unroll
        for (int ks = 0; ks < 2; ks++) {
            uint32_t ah[4][4], al[4][4];
#pragma unroll
            for (int i = 0; i < 4; i++) {
                const uint32_t off = ((aRow + i * 16) * LDS + ks * 16 + aKh) * 2;
                ldm_x4(ah[i], sb + off);
                ldm_x4(al[i], sb + TILE_E * 2 + off);
            }
#pragma unroll
            for (int j = 0; j < 4; j++) {
                uint32_t bh[2], bl[2];
                const uint32_t off = ((bRow + j * 8) * LDS + ks * 16 + bKh) * 2;
                ldm_x2(bh, sb + TILE_E * 4 + off);
                ldm_x2(bl, sb + TILE_E * 6 + off);
#pragma unroll
                for (int i = 0; i < 4; i++) {
                    float* d = &acc[(i * 4 + j) * 4];
                    mma_bf16(d, ah[i], bh);
                    mma_bf16(d, ah[i], bl);
                    mma_bf16(d, al[i], bh);
                }
            }
        }
        __syncthreads();
    }

    // ---- epilogue: accum regs -> smem (fp32, coalesce) -> gmem
    float* smf = (float*)sm;
    {
        const int r0 = lane >> 2;
        const int cc = (lane & 3) * 2;
#pragma unroll
        for (int i = 0; i < 4; i++)
#pragma unroll
            for (int j = 0; j < 4; j++) {
                const float* d = &acc[(i * 4 + j) * 4];
                const int rr = wm + i * 16 + r0;
                const int col = wn + j * 8 + cc;
                smf[rr * 132 + col]       = d[0];
                smf[rr * 132 + col + 1]   = d[1];
                smf[(rr + 8) * 132 + col]     = d[2];
                smf[(rr + 8) * 132 + col + 1] = d[3];
            }
    }
    __syncthreads();

    // C may be 4-byte aligned only (G_node base offset +9 floats): pick store width
    const bool c_vec = ((((uintptr_t)C) & 15) == 0) && ((ldc & 3) == 0);

#pragma unroll
    for (int it = 0; it < 16; it++) {
        const int f4 = it * 256 + tid;
        const int rr = f4 >> 5;
        const int c4 = (f4 & 31) * 4;
        float4 v = *(float4*)&smf[rr * 132 + c4];
        const int row = row0 + rr;
        const int gn  = n0 + c4;
        float o[4];
        float dv[4] = {0.f, 0.f, 0.f, 0.f};
        if (mode == EPI_ADD || mode == EPI_MUL) {
            float4 d4 = *(const float4*)(Dop + (size_t)row * ldd + gn);
            dv[0] = d4.x; dv[1] = d4.y; dv[2] = d4.z; dv[3] = d4.w;
        }
#pragma unroll
        for (int q = 0; q < 4; q++) {
            const float val = (&v.x)[q];
            const float bv = bias ? bias[gn + q] : 0.f;
            float res;
            if (mode == EPI_SIG)      res = 1.f / (1.f + expf(-(val + bv)));
            else if (mode == EPI_ADD) res = val + dv[q] + bv;
            else if (mode == EPI_MUL) res = val * dv[q] + bv;
            else if (mode == EPI_OMZ) res = 1.f - (val + bv);
            else                      res = val + bv;
            o[q] = res;
        }
        float* cp = C + (size_t)row * ldc + gn;
        if (c_vec) {
            *(float4*)cp = make_float4(o[0], o[1], o[2], o[3]);
        } else {
            cp[0] = o[0]; cp[1] = o[1]; cp[2] = o[2]; cp[3] = o[3];
        }
        if (Obh) {
            __nv_bfloat16 hh[4], ll[4];
#pragma unroll
            for (int q = 0; q < 4; q++) {
                hh[q] = __float2bfloat16(o[q]);
                ll[q] = __float2bfloat16(o[q] - __bfloat162float(hh[q]));
            }
            __nv_bfloat162* ph = (__nv_bfloat162*)(Obh + (size_t)row * ldob + gn);
            __nv_bfloat162* pl = (__nv_bfloat162*)(Obl + (size_t)row * ldob + gn);
            ph[0] = __nv_bfloat162{hh[0], hh[1]};
            ph[1] = __nv_bfloat162{hh[2], hh[3]};
            pl[0] = __nv_bfloat162{ll[0], ll[1]};
            pl[1] = __nv_bfloat162{ll[2], ll[3]};
        }
    }
}

// ---------------- weight prep: transpose + bf16 split ----------------
__global__ __launch_bounds__(256)
void prep_weights(const float* __restrict__ L, const float* __restrict__ R,
                  __nv_bfloat16* __restrict__ Lh, __nv_bfloat16* __restrict__ Ll,
                  __nv_bfloat16* __restrict__ Rh, __nv_bfloat16* __restrict__ Rl)
{
    __shared__ float t[32][33];
    const int mz = blockIdx.z;
    const float* src = (mz < 4) ? L : R;
    __nv_bfloat16* dh = (mz < 4) ? Lh : Rh;
    __nv_bfloat16* dl = (mz < 4) ? Ll : Rl;
    const int k = mz & 3;
    const int h0 = blockIdx.y * 32, d0 = blockIdx.x * 32;
    const int tx = threadIdx.x & 31, ty = threadIdx.x >> 5;

    for (int i = 0; i < 32; i += 8)
        t[ty + i][tx] = src[k * 65536 + (h0 + ty + i) * 256 + d0 + tx];
    __syncthreads();
    for (int i = 0; i < 32; i += 8) {
        const float v = t[tx][ty + i];
        const __nv_bfloat16 hi = __float2bfloat16(v);
        const __nv_bfloat16 lo = __float2bfloat16(v - __bfloat162float(hi));
        dh[k * 65536 + (d0 + ty + i) * 256 + h0 + tx] = hi;
        dl[k * 65536 + (d0 + ty + i) * 256 + h0 + tx] = lo;
    }
}

// ---------------- fp32 -> bf16 hi/lo split ----------------
__global__ __launch_bounds__(256)
void conv_split(const float* __restrict__ in, __nv_bfloat16* __restrict__ hi,
                __nv_bfloat16* __restrict__ lo, int n)
{
    const int i = blockIdx.x * 256 + threadIdx.x;
    if (i < n) {
        const float v = in[i];
        const __nv_bfloat16 h = __float2bfloat16(v);
        hi[i] = h;
        lo[i] = __float2bfloat16(v - __bfloat162float(h));
    }
}

// ---------------- mixture ----------------
__global__ __launch_bounds__(256)
void mixture_kernel(const float* __restrict__ cand,
                    const float* __restrict__ Ws,
                    float* __restrict__ out1, int ldo1,
                    float* __restrict__ out2,
                    __nv_bfloat16* __restrict__ obh, __nv_bfloat16* __restrict__ obl,
                    float* __restrict__ rowscores)
{
    const int b = blockIdx.x;
    const int d = threadIdx.x;
    const int lane = d & 31, warp = d >> 5;

    const float* cr = cand + (size_t)b * 1024;
    const float c0 = cr[d];
    const float c1 = cr[256 + d];
    const float c2 = cr[512 + d];
    const float c3 = cr[768 + d];
    const float wv = Ws[d];

    float s0 = c0 * wv, s1 = c1 * wv, s2 = c2 * wv, s3 = c3 * wv;
#pragma unroll
    for (int o = 16; o > 0; o >>= 1) {
        s0 += __shfl_down_sync(0xffffffffu, s0, o);
        s1 += __shfl_down_sync(0xffffffffu, s1, o);
        s2 += __shfl_down_sync(0xffffffffu, s2, o);
        s3 += __shfl_down_sync(0xffffffffu, s3, o);
    }
    __shared__ float red[8][4];
    __shared__ float sc[4];
    if (lane == 0) { red[warp][0] = s0; red[warp][1] = s1; red[warp][2] = s2; red[warp][3] = s3; }
    __syncthreads();
    if (d < 4) {
        float t = 0.f;
#pragma unroll
        for (int w = 0; w < 8; w++) t += red[w][d];
        sc[d] = t;
        rowscores[d * BATCH + b] = t;
    }
    __syncthreads();

    const float a0 = sc[0], a1 = sc[1], a2 = sc[2], a3 = sc[3];
    const float mx = fmaxf(fmaxf(a0, a1), fmaxf(a2, a3));
    const float e0 = expf(a0 - mx), e1 = expf(a1 - mx);
    const float e2 = expf(a2 - mx), e3 = expf(a3 - mx);
    const float inv = 1.f / (e0 + e1 + e2 + e3);
    const float o = (e0 * c0 + e1 * c1 + e2 * c2 + e3 * c3) * inv;

    out1[(size_t)b * ldo1 + d] = o;
    if (out2) out2[(size_t)b * HID + d] = o;
    if (obh) {
        const __nv_bfloat16 h = __float2bfloat16(o);
        obh[(size_t)b * HID + d] = h;
        obl[(size_t)b * HID + d] = __float2bfloat16(o - __bfloat162float(h));
    }
}

// ---------------- z2 = z1 copy ----------------
__global__ void copy_z2_kernel(float* __restrict__ out)
{
    const int b = blockIdx.x;
    const int d = threadIdx.x;
    out[OFF_GNODE + (size_t)(b * 9 + 2) * HID + d] = out[OFF_GNODE + (size_t)(b * 9 + 0) * HID + d];
}

// ---------------- finalize ----------------
__global__ __launch_bounds__(256)
void finalize_kernel(const float* __restrict__ rs, float* __restrict__ out)
{
    __shared__ double tmp[256];
    __shared__ double ssum[24];
    const int tid = threadIdx.x;

    for (int idx = 0; idx < 24; idx++) {
        double p = 0.0;
        for (int i = tid; i < BATCH; i += 256) p += (double)rs[idx * BATCH + i];
        tmp[tid] = p;
        __syncthreads();
        for (int o = 128; o > 0; o >>= 1) {
            if (tid < o) tmp[tid] += tmp[tid + o];
            __syncthreads();
        }
        if (tid == 0) ssum[idx] = tmp[0];
        __syncthreads();
    }

    if (tid == 0) {
        out[OFF_GS + 0] = 0.f;
        out[OFF_GS + 1] = 1.f;
        out[OFF_GS + 2] = 0.f;
        for (int s = 0; s < 6; s++) {
            double best = ssum[s * 4]; int bi = 0;
            for (int k = 1; k < 4; k++)
                if (ssum[s * 4 + k] > best) { best = ssum[s * 4 + k]; bi = k; }
            double second = -1e300;
            for (int k = 0; k < 4; k++)
                if (k != bi && ssum[s * 4 + k] > second) second = ssum[s * 4 + k];
            out[OFF_GS + 3 + s] = (float)bi;
            out[OFF_MARG + s]   = (float)(best - second);
        }
    }
}

// ---------------- launcher ----------------
extern "C" void kernel_launch(void* const* d_in, const int* in_sizes, int n_in,
                              void* d_out, int out_size)
{
    const float* x  = (const float*)d_in[0];
    const float* h  = (const float*)d_in[1];
    const float* L  = (const float*)d_in[2];
    const float* R  = (const float*)d_in[3];
    const float* bb = (const float*)d_in[4];
    const float* Ws = (const float*)d_in[5];
    float* out = (float*)d_out;

    static bool attr_done = false;
    if (!attr_done) {
        cudaFuncSetAttribute(tc_gemm, cudaFuncAttributeMaxDynamicSharedMemorySize, DYN_SMEM);
        attr_done = true;
    }

    float *p_hL, *p_tmp, *p_cand, *p_rows;
    __nv_bfloat16 *p_bf, *p_w;
    cudaGetSymbolAddress((void**)&p_hL,   g_hL);
    cudaGetSymbolAddress((void**)&p_tmp,  g_tmp);
    cudaGetSymbolAddress((void**)&p_cand, g_cand);
    cudaGetSymbolAddress((void**)&p_rows, g_rows);
    cudaGetSymbolAddress((void**)&p_bf,   g_bf);
    cudaGetSymbolAddress((void**)&p_w,    g_w);

    __nv_bfloat16* xh   = p_bf + 0ull  * UNIT;
    __nv_bfloat16* xl   = p_bf + 1ull  * UNIT;
    __nv_bfloat16* hh   = p_bf + 2ull  * UNIT;
    __nv_bfloat16* hl   = p_bf + 3ull  * UNIT;
    __nv_bfloat16* z1rh = p_bf + 4ull  * UNIT;   // 2 units, ld 512
    __nv_bfloat16* z1rl = p_bf + 6ull  * UNIT;
    __nv_bfloat16* rhh  = p_bf + 8ull  * UNIT;
    __nv_bfloat16* rhl  = p_bf + 9ull  * UNIT;
    __nv_bfloat16* hth  = p_bf + 10ull * UNIT;
    __nv_bfloat16* htl  = p_bf + 11ull * UNIT;
    __nv_bfloat16* omh  = p_bf + 12ull * UNIT;
    __nv_bfloat16* oml  = p_bf + 13ull * UNIT;
    __nv_bfloat16* zth  = p_bf + 14ull * UNIT;
    __nv_bfloat16* ztl  = p_bf + 15ull * UNIT;
    __nv_bfloat16* z2hh = p_bf + 16ull * UNIT;
    __nv_bfloat16* z2hl = p_bf + 17ull * UNIT;

    __nv_bfloat16* Lh = p_w + 0ull * WUNIT;
    __nv_bfloat16* Ll = p_w + 1ull * WUNIT;
    __nv_bfloat16* Rh = p_w + 2ull * WUNIT;
    __nv_bfloat16* Rl = p_w + 3ull * WUNIT;

    float* gnode = out + OFF_GNODE;
    const dim3 blk(256);
    const dim3 gW(8, 8, 8);
    const dim3 g512(4, BATCH / 128);
    const dim3 g1024(8, BATCH / 128);
    const int NCONV = BATCH * HID;

    prep_weights<<<gW, blk>>>(L, R, Lh, Ll, Rh, Rl);
    conv_split<<<NCONV / 256, blk>>>(x, xh, xl, NCONV);
    conv_split<<<NCONV / 256, blk>>>(h, hh, hl, NCONV);

    // stage 0: [z1 | r] = sig(x@L + h@R + b), cols 0..511
    tc_gemm<<<g512, blk, DYN_SMEM>>>(xh, xl, 256, Lh, Ll, hh, hl, 256, Rh, Rl, 2,
                                     bb, (const float*)0, 0,
                                     gnode, GROW, z1rh, z1rl, 512, EPI_SIG);
    copy_z2_kernel<<<BATCH, blk>>>(out);

    // hL = h @ [L0..L3]
    tc_gemm<<<g1024, blk, DYN_SMEM>>>(hh, hl, 256, Lh, Ll,
                                      (const __nv_bfloat16*)0, (const __nv_bfloat16*)0, 0,
                                      (const __nv_bfloat16*)0, (const __nv_bfloat16*)0, 1,
                                      (const float*)0, (const float*)0, 0,
                                      p_hL, 1024, (__nv_bfloat16*)0, (__nv_bfloat16*)0, 0, EPI_NONE);

    // stage A: cand = hL + r@R + b -> rh (slot 3)
    tc_gemm<<<g1024, blk, DYN_SMEM>>>(z1rh + 256, z1rl + 256, 512, Rh, Rl,
                                      (const __nv_bfloat16*)0, (const __nv_bfloat16*)0, 0,
                                      (const __nv_bfloat16*)0, (const __nv_bfloat16*)0, 1,
                                      bb, p_hL, 1024,
                                      p_cand, 1024, (__nv_bfloat16*)0, (__nv_bfloat16*)0, 0, EPI_ADD);
    mixture_kernel<<<BATCH, blk>>>(p_cand, Ws, gnode + 3 * HID, GROW, (float*)0,
                                   rhh, rhl, p_rows + 0 * 4 * BATCH);

    // stage B: cand = x@L + rh@R + b -> h_tilde (slot 4)
    tc_gemm<<<g1024, blk, DYN_SMEM>>>(xh, xl, 256, Lh, Ll, rhh, rhl, 256, Rh, Rl, 2,
                                      bb, (const float*)0, 0,
                                      p_cand, 1024, (__nv_bfloat16*)0, (__nv_bfloat16*)0, 0, EPI_NONE);
    mixture_kernel<<<BATCH, blk>>>(p_cand, Ws, gnode + 4 * HID, GROW, (float*)0,
                                   hth, htl, p_rows + 1 * 4 * BATCH);

    // stage C: cand = 1 - (z1@R + b) -> oneMinusZ1 (slot 5)
    tc_gemm<<<g1024, blk, DYN_SMEM>>>(z1rh, z1rl, 512, Rh, Rl,
                                      (const __nv_bfloat16*)0, (const __nv_bfloat16*)0, 0,
                                      (const __nv_bfloat16*)0, (const __nv_bfloat16*)0, 1,
                                      bb, (const float*)0, 0,
                                      p_cand, 1024, (__nv_bfloat16*)0, (__nv_bfloat16*)0, 0, EPI_OMZ);
    mixture_kernel<<<BATCH, blk>>>(p_cand, Ws, gnode + 5 * HID, GROW, (float*)0,
                                   omh, oml, p_rows + 2 * 4 * BATCH);

    // stage D: cand = (h_tilde@L) * (omz@R) + b -> zh_tilde (slot 6)
    tc_gemm<<<g1024, blk, DYN_SMEM>>>(hth, htl, 256, Lh, Ll,
                                      (const __nv_bfloat16*)0, (const __nv_bfloat16*)0, 0,
                                      (const __nv_bfloat16*)0, (const __nv_bfloat16*)0, 1,
                                      (const float*)0, (const float*)0, 0,
                                      p_tmp, 1024, (__nv_bfloat16*)0, (__nv_bfloat16*)0, 0, EPI_NONE);
    tc_gemm<<<g1024, blk, DYN_SMEM>>>(omh, oml, 256, Rh, Rl,
                                      (const __nv_bfloat16*)0, (const __nv_bfloat16*)0, 0,
                                      (const __nv_bfloat16*)0, (const __nv_bfloat16*)0, 1,
                                      bb, p_tmp, 1024,
                                      p_cand, 1024, (__nv_bfloat16*)0, (__nv_bfloat16*)0, 0, EPI_MUL);
    mixture_kernel<<<BATCH, blk>>>(p_cand, Ws, gnode + 6 * HID, GROW, (float*)0,
                                   zth, ztl, p_rows + 3 * 4 * BATCH);

    // stage E: cand = hL * (z2@R) + b -> z2h (slot 7)   (z2 == z1)
    tc_gemm<<<g1024, blk, DYN_SMEM>>>(z1rh, z1rl, 512, Rh, Rl,
                                      (const __nv_bfloat16*)0, (const __nv_bfloat16*)0, 0,
                                      (const __nv_bfloat16*)0, (const __nv_bfloat16*)0, 1,
                                      bb, p_hL, 1024,
                                      p_cand, 1024, (__nv_bfloat16*)0, (__nv_bfloat16*)0, 0, EPI_MUL);
    mixture_kernel<<<BATCH, blk>>>(p_cand, Ws, gnode + 7 * HID, GROW, (float*)0,
                                   z2hh, z2hl, p_rows + 4 * 4 * BATCH);

    // stage F: cand = zh_tilde@L + z2h@R + b -> h_next (slot 8 + output)
    tc_gemm<<<g1024, blk, DYN_SMEM>>>(zth, ztl, 256, Lh, Ll, z2hh, z2hl, 256, Rh, Rl, 2,
                                      bb, (const float*)0, 0,
                                      p_cand, 1024, (__nv_bfloat16*)0, (__nv_bfloat16*)0, 0, EPI_NONE);
    mixture_kernel<<<BATCH, blk>>>(p_cand, Ws, gnode + 8 * HID, GROW, out + OFF_HNEXT,
                                   (__nv_bfloat16*)0, (__nv_bfloat16*)0, p_rows + 5 * 4 * BATCH);

    finalize_kernel<<<1, blk>>>(p_rows, out);
}

// round 5
// speedup vs baseline: 3.5293x; 1.3984x over previous
#include <cuda_runtime.h>
#include <cuda_bf16.h>
#include <math.h>
#include <stdint.h>

// ---------------- problem constants ----------------
#define BATCH 16384
#define HID   256

// output layout (flat float32 concat of the reference tuple)
#define OFF_HNEXT 0
#define OFF_GS    (BATCH * HID)
#define OFF_GNODE (OFF_GS + 9)
#define OFF_MARG  (OFF_GNODE + BATCH * 9 * HID)
#define GROW      (9 * HID)

// ---------------- epilogue modes ----------------
#define EPI_NONE 0
#define EPI_SIG  1
#define EPI_ADD  2   // acc + D + bias
#define EPI_MUL  3   // acc * D + bias
#define EPI_OMZ  4   // 1 - (acc + bias)

// c3 modes for mixture (identity slice)
#define C3_ADD 0     // P + Q + b3
#define C3_OMZ 1     // 1 - (P + b3)
#define C3_MUL 2     // P*Q + b3

// ---------------- scratch (device globals) ----------------
__device__ float g_hL[BATCH * 1024];
__device__ float g_tmp[BATCH * 1024];
__device__ float g_cand[BATCH * 1024];
__device__ float g_rows[6 * 4 * BATCH];
__device__ double g_ssum[24];

#define UNIT (BATCH * HID)
__device__ __nv_bfloat16 g_bf[18ull * UNIT];
#define WUNIT (4 * 256 * 256)
__device__ __nv_bfloat16 g_w[4 * WUNIT];

// ---------------- helpers ----------------
__device__ __forceinline__ uint32_t smem_u32(const void* p) {
    uint32_t a;
    asm("{ .reg .u64 t; cvta.to.shared.u64 t, %1; cvt.u32.u64 %0, t; }" : "=r"(a) : "l"(p));
    return a;
}

#define CP16(saddr, gaddr) \
    asm volatile("cp.async.ca.shared.global [%0], [%1], 16;" :: "r"(saddr), "l"(gaddr))
#define CP_COMMIT() asm volatile("cp.async.commit_group;")
#define CP_WAIT1()  asm volatile("cp.async.wait_group 1;")
#define CP_WAIT0()  asm volatile("cp.async.wait_group 0;")

__device__ __forceinline__ void ldm_x4(uint32_t* r, uint32_t addr) {
    asm volatile("ldmatrix.sync.aligned.m8n8.x4.shared.b16 {%0,%1,%2,%3}, [%4];"
                 : "=r"(r[0]), "=r"(r[1]), "=r"(r[2]), "=r"(r[3]) : "r"(addr));
}
__device__ __forceinline__ void ldm_x2(uint32_t* r, uint32_t addr) {
    asm volatile("ldmatrix.sync.aligned.m8n8.x2.shared.b16 {%0,%1}, [%2];"
                 : "=r"(r[0]), "=r"(r[1]) : "r"(addr));
}
__device__ __forceinline__ void mma_bf16(float* d, const uint32_t* a, const uint32_t* b) {
    asm volatile(
        "mma.sync.aligned.m16n8k16.row.col.f32.bf16.bf16.f32 "
        "{%0,%1,%2,%3}, {%4,%5,%6,%7}, {%8,%9}, {%0,%1,%2,%3};"
        : "+f"(d[0]), "+f"(d[1]), "+f"(d[2]), "+f"(d[3])
        : "r"(a[0]), "r"(a[1]), "r"(a[2]), "r"(a[3]), "r"(b[0]), "r"(b[1]));
}

// ---------------- HMMA GEMM ----------------
#define LDS 40
#define TILE_E (128 * LDS)
#define STAGE_E (4 * TILE_E)
#define DYN_SMEM (2 * STAGE_E * 2)         // 81920 bytes

__global__ __launch_bounds__(256, 2)
void tc_gemm(const __nv_bfloat16* __restrict__ A1h, const __nv_bfloat16* __restrict__ A1l, int lda1,
             const __nv_bfloat16* __restrict__ W1h, const __nv_bfloat16* __restrict__ W1l,
             const __nv_bfloat16* __restrict__ A2h, const __nv_bfloat16* __restrict__ A2l, int lda2,
             const __nv_bfloat16* __restrict__ W2h, const __nv_bfloat16* __restrict__ W2l,
             int nPair,
             const float* __restrict__ bias,
             const float* __restrict__ Dop, int ldd,
             float* __restrict__ C, int ldc, int mode,
             const float* __restrict__ D2op, int ldd2,
             float* __restrict__ C2, int ldc2, int mode2,
             __nv_bfloat16* __restrict__ Obh, __nv_bfloat16* __restrict__ Obl, int ldob,
             int dupz2)
{
    extern __shared__ __nv_bfloat16 sm[];
    const int tid  = threadIdx.x;
    const int wid  = tid >> 5;
    const int lane = tid & 31;

    const int row0   = blockIdx.y * 128;
    const int n0     = blockIdx.x * 128;
    const int kslice = n0 >> 8;
    const int wc0    = n0 & 255;

    const __nv_bfloat16* wBh1 = W1h + kslice * 65536;
    const __nv_bfloat16* wBl1 = W1l + kslice * 65536;
    const __nv_bfloat16* wBh2 = W2h ? W2h + kslice * 65536 : (const __nv_bfloat16*)0;
    const __nv_bfloat16* wBl2 = W2l ? W2l + kslice * 65536 : (const __nv_bfloat16*)0;

    const uint32_t smb = smem_u32(sm);
    const int NCH = nPair * 8;

    const int lrow = tid >> 1;
    const int lkof = (tid & 1) * 16;

    float acc[64];
#pragma unroll
    for (int i = 0; i < 64; i++) acc[i] = 0.f;

    const int wm = (wid >> 2) * 64;
    const int wn = (wid & 3) * 32;

    auto load_chunk = [&](int c, int buf) {
        const __nv_bfloat16 *pAh, *pAl, *pWh, *pWl;
        int lda;
        if (c < 8) { pAh = A1h; pAl = A1l; lda = lda1; pWh = wBh1; pWl = wBl1; }
        else       { pAh = A2h; pAl = A2l; lda = lda2; pWh = wBh2; pWl = wBl2; }
        const int k0 = (c & 7) * 32;
        const uint32_t sb = smb + buf * STAGE_E * 2;
        const uint32_t so = (lrow * LDS + lkof) * 2;
        const __nv_bfloat16* gA = pAh + (size_t)(row0 + lrow) * lda + k0 + lkof;
        CP16(sb + so,      gA);
        CP16(sb + so + 16, gA + 8);
        const __nv_bfloat16* gAl = pAl + (size_t)(row0 + lrow) * lda + k0 + lkof;
        CP16(sb + TILE_E * 2 + so,      gAl);
        CP16(sb + TILE_E * 2 + so + 16, gAl + 8);
        const __nv_bfloat16* gW = pWh + (size_t)(wc0 + lrow) * 256 + k0 + lkof;
        CP16(sb + TILE_E * 4 + so,      gW);
        CP16(sb + TILE_E * 4 + so + 16, gW + 8);
        const __nv_bfloat16* gWl = pWl + (size_t)(wc0 + lrow) * 256 + k0 + lkof;
        CP16(sb + TILE_E * 6 + so,      gWl);
        CP16(sb + TILE_E * 6 + so + 16, gWl + 8);
        CP_COMMIT();
    };

    load_chunk(0, 0);

    for (int c = 0; c < NCH; c++) {
        if (c + 1 < NCH) {
            load_chunk(c + 1, (c + 1) & 1);
            CP_WAIT1();
        } else {
            CP_WAIT0();
        }
        __syncthreads();

        const uint32_t sb = smb + (c & 1) * STAGE_E * 2;
        const uint32_t aRow = (uint32_t)(wm + (lane & 15));
        const uint32_t aKh  = (uint32_t)((lane >> 4) * 8);
        const uint32_t bRow = (uint32_t)(wn + (lane & 7));
        const uint32_t bKh  = (uint32_t)(((lane >> 3) & 1) * 8);

#pragma unroll
        for (int ks = 0; ks < 2; ks++) {
            uint32_t ah[4][4], al[4][4];
#pragma unroll
            for (int i = 0; i < 4; i++) {
                const uint32_t off = ((aRow + i * 16) * LDS + ks * 16 + aKh) * 2;
                ldm_x4(ah[i], sb + off);
                ldm_x4(al[i], sb + TILE_E * 2 + off);
            }
#pragma unroll
            for (int j = 0; j < 4; j++) {
                uint32_t bh[2], bl[2];
                const uint32_t off = ((bRow + j * 8) * LDS + ks * 16 + bKh) * 2;
                ldm_x2(bh, sb + TILE_E * 4 + off);
                ldm_x2(bl, sb + TILE_E * 6 + off);
#pragma unroll
                for (int i = 0; i < 4; i++) {
                    float* d = &acc[(i * 4 + j) * 4];
                    mma_bf16(d, ah[i], bh);
                    mma_bf16(d, ah[i], bl);
                    mma_bf16(d, al[i], bh);
                }
            }
        }
        __syncthreads();
    }

    // ---- epilogue: regs -> smem (coalesce) -> gmem
    float* smf = (float*)sm;
    {
        const int r0 = lane >> 2;
        const int cc = (lane & 3) * 2;
#pragma unroll
        for (int i = 0; i < 4; i++)
#pragma unroll
            for (int j = 0; j < 4; j++) {
                const float* d = &acc[(i * 4 + j) * 4];
                const int rr = wm + i * 16 + r0;
                const int col = wn + j * 8 + cc;
                smf[rr * 132 + col]       = d[0];
                smf[rr * 132 + col + 1]   = d[1];
                smf[(rr + 8) * 132 + col]     = d[2];
                smf[(rr + 8) * 132 + col + 1] = d[3];
            }
    }
    __syncthreads();

    const bool c_vec  = ((((uintptr_t)C) & 15) == 0) && ((ldc & 3) == 0);
    const bool c2_vec = C2 && ((((uintptr_t)C2) & 15) == 0) && ((ldc2 & 3) == 0);

#pragma unroll
    for (int it = 0; it < 16; it++) {
        const int f4 = it * 256 + tid;
        const int rr = f4 >> 5;
        const int c4 = (f4 & 31) * 4;
        float4 v = *(float4*)&smf[rr * 132 + c4];
        const int row = row0 + rr;
        const int gn  = n0 + c4;
        float o[4];
        float dv[4] = {0.f, 0.f, 0.f, 0.f};
        if (mode == EPI_ADD || mode == EPI_MUL) {
            float4 d4 = *(const float4*)(Dop + (size_t)row * ldd + gn);
            dv[0] = d4.x; dv[1] = d4.y; dv[2] = d4.z; dv[3] = d4.w;
        }
#pragma unroll
        for (int q = 0; q < 4; q++) {
            const float val = (&v.x)[q];
            const float bv = bias ? bias[gn + q] : 0.f;
            float res;
            if (mode == EPI_SIG)      res = 1.f / (1.f + expf(-(val + bv)));
            else if (mode == EPI_ADD) res = val + dv[q] + bv;
            else if (mode == EPI_MUL) res = val * dv[q] + bv;
            else if (mode == EPI_OMZ) res = 1.f - (val + bv);
            else                      res = val + bv;
            o[q] = res;
        }
        float* cp = C + (size_t)row * ldc + gn;
        if (c_vec) *(float4*)cp = make_float4(o[0], o[1], o[2], o[3]);
        else { cp[0] = o[0]; cp[1] = o[1]; cp[2] = o[2]; cp[3] = o[3]; }

        if (dupz2 && gn < 256) {   // z2 = z1 duplicate into slot 2
            float* zp = C + (size_t)row * ldc + 512 + gn;
            zp[0] = o[0]; zp[1] = o[1]; zp[2] = o[2]; zp[3] = o[3];
        }

        if (C2) {
            float o2[4];
            float dv2[4] = {0.f, 0.f, 0.f, 0.f};
            if (mode2 == EPI_ADD || mode2 == EPI_MUL) {
                float4 d4 = *(const float4*)(D2op + (size_t)row * ldd2 + gn);
                dv2[0] = d4.x; dv2[1] = d4.y; dv2[2] = d4.z; dv2[3] = d4.w;
            }
#pragma unroll
            for (int q = 0; q < 4; q++) {
                const float val = (&v.x)[q];
                const float bv = bias ? bias[gn + q] : 0.f;
                float res;
                if (mode2 == EPI_SIG)      res = 1.f / (1.f + expf(-(val + bv)));
                else if (mode2 == EPI_ADD) res = val + dv2[q] + bv;
                else if (mode2 == EPI_MUL) res = val * dv2[q] + bv;
                else if (mode2 == EPI_OMZ) res = 1.f - (val + bv);
                else                       res = val + bv;
                o2[q] = res;
            }
            float* cp2 = C2 + (size_t)row * ldc2 + gn;
            if (c2_vec) *(float4*)cp2 = make_float4(o2[0], o2[1], o2[2], o2[3]);
            else { cp2[0] = o2[0]; cp2[1] = o2[1]; cp2[2] = o2[2]; cp2[3] = o2[3]; }
        }

        if (Obh) {
            __nv_bfloat16 hh[4], ll[4];
#pragma unroll
            for (int q = 0; q < 4; q++) {
                hh[q] = __float2bfloat16(o[q]);
                ll[q] = __float2bfloat16(o[q] - __bfloat162float(hh[q]));
            }
            __nv_bfloat162* ph = (__nv_bfloat162*)(Obh + (size_t)row * ldob + gn);
            __nv_bfloat162* pl = (__nv_bfloat162*)(Obl + (size_t)row * ldob + gn);
            ph[0] = __nv_bfloat162{hh[0], hh[1]};
            ph[1] = __nv_bfloat162{hh[2], hh[3]};
            pl[0] = __nv_bfloat162{ll[0], ll[1]};
            pl[1] = __nv_bfloat162{ll[2], ll[3]};
        }
    }
}

// ---------------- weight prep: transpose + bf16 split ----------------
__global__ __launch_bounds__(256)
void prep_weights(const float* __restrict__ L, const float* __restrict__ R,
                  __nv_bfloat16* __restrict__ Lh, __nv_bfloat16* __restrict__ Ll,
                  __nv_bfloat16* __restrict__ Rh, __nv_bfloat16* __restrict__ Rl)
{
    __shared__ float t[32][33];
    const int mz = blockIdx.z;
    const float* src = (mz < 4) ? L : R;
    __nv_bfloat16* dh = (mz < 4) ? Lh : Rh;
    __nv_bfloat16* dl = (mz < 4) ? Ll : Rl;
    const int k = mz & 3;
    const int h0 = blockIdx.y * 32, d0 = blockIdx.x * 32;
    const int tx = threadIdx.x & 31, ty = threadIdx.x >> 5;

    for (int i = 0; i < 32; i += 8)
        t[ty + i][tx] = src[k * 65536 + (h0 + ty + i) * 256 + d0 + tx];
    __syncthreads();
    for (int i = 0; i < 32; i += 8) {
        const float v = t[tx][ty + i];
        const __nv_bfloat16 hi = __float2bfloat16(v);
        const __nv_bfloat16 lo = __float2bfloat16(v - __bfloat162float(hi));
        dh[k * 65536 + (d0 + ty + i) * 256 + h0 + tx] = hi;
        dl[k * 65536 + (d0 + ty + i) * 256 + h0 + tx] = lo;
    }
}

// ---------------- fp32 -> bf16 hi/lo split (x and h in one launch) ------
__global__ __launch_bounds__(256)
void conv_split2(const float* __restrict__ x, const float* __restrict__ h,
                 __nv_bfloat16* __restrict__ xh, __nv_bfloat16* __restrict__ xl,
                 __nv_bfloat16* __restrict__ hh, __nv_bfloat16* __restrict__ hl)
{
    const int i = blockIdx.x * 256 + threadIdx.x;
    const int n = BATCH * HID;
    const float v = (i < n) ? x[i] : h[i - n];
    __nv_bfloat16* dh = (i < n) ? xh : hh;
    __nv_bfloat16* dl = (i < n) ? xl : hl;
    const int idx = (i < n) ? i : i - n;
    const __nv_bfloat16 hi = __float2bfloat16(v);
    dh[idx] = hi;
    dl[idx] = __float2bfloat16(v - __bfloat162float(hi));
}

// ---------------- mixture: warp-per-row, identity slice computed inline --
__global__ __launch_bounds__(256)
void mixture_kernel(const float* __restrict__ cand, int ldcand,     // slices 0..2
                    const float* __restrict__ P, int ldp,
                    const float* __restrict__ Q, int ldq,
                    int c3mode,
                    const float* __restrict__ b3,                   // bias[3]
                    const float* __restrict__ Ws,
                    float* __restrict__ out1, int ldo1,
                    float* __restrict__ out2,
                    __nv_bfloat16* __restrict__ obh, __nv_bfloat16* __restrict__ obl,
                    float* __restrict__ rowscores)
{
    const int warp = threadIdx.x >> 5;
    const int lane = threadIdx.x & 31;
    const int b = blockIdx.x * 8 + warp;

    const float* cr = cand + (size_t)b * ldcand;
    const float* pr = P + (size_t)b * ldp;
    const float* qr = Q ? Q + (size_t)b * ldq : (const float*)0;

    float c[2][4][4];   // [group][slice][elem]
    float s0 = 0.f, s1 = 0.f, s2 = 0.f, s3 = 0.f;

#pragma unroll
    for (int g = 0; g < 2; g++) {
        const int j = g * 128 + lane * 4;
        float4 v0 = *(const float4*)(cr + j);
        float4 v1 = *(const float4*)(cr + 256 + j);
        float4 v2 = *(const float4*)(cr + 512 + j);
        float4 bw = *(const float4*)(b3 + j);
        float4 wv = *(const float4*)(Ws + j);
        float p0 = pr[j], p1 = pr[j + 1], p2 = pr[j + 2], p3 = pr[j + 3];
        float c3v[4];
        if (c3mode == C3_ADD) {
            c3v[0] = p0 + qr[j]     + bw.x;
            c3v[1] = p1 + qr[j + 1] + bw.y;
            c3v[2] = p2 + qr[j + 2] + bw.z;
            c3v[3] = p3 + qr[j + 3] + bw.w;
        } else if (c3mode == C3_OMZ) {
            c3v[0] = 1.f - (p0 + bw.x);
            c3v[1] = 1.f - (p1 + bw.y);
            c3v[2] = 1.f - (p2 + bw.z);
            c3v[3] = 1.f - (p3 + bw.w);
        } else {
            c3v[0] = p0 * qr[j]     + bw.x;
            c3v[1] = p1 * qr[j + 1] + bw.y;
            c3v[2] = p2 * qr[j + 2] + bw.z;
            c3v[3] = p3 * qr[j + 3] + bw.w;
        }
        c[g][0][0] = v0.x; c[g][0][1] = v0.y; c[g][0][2] = v0.z; c[g][0][3] = v0.w;
        c[g][1][0] = v1.x; c[g][1][1] = v1.y; c[g][1][2] = v1.z; c[g][1][3] = v1.w;
        c[g][2][0] = v2.x; c[g][2][1] = v2.y; c[g][2][2] = v2.z; c[g][2][3] = v2.w;
        c[g][3][0] = c3v[0]; c[g][3][1] = c3v[1]; c[g][3][2] = c3v[2]; c[g][3][3] = c3v[3];
        const float w0 = wv.x, w1 = wv.y, w2 = wv.z, w3 = wv.w;
        s0 += v0.x * w0 + v0.y * w1 + v0.z * w2 + v0.w * w3;
        s1 += v1.x * w0 + v1.y * w1 + v1.z * w2 + v1.w * w3;
        s2 += v2.x * w0 + v2.y * w1 + v2.z * w2 + v2.w * w3;
        s3 += c3v[0] * w0 + c3v[1] * w1 + c3v[2] * w2 + c3v[3] * w3;
    }

#pragma unroll
    for (int o = 16; o > 0; o >>= 1) {
        s0 += __shfl_xor_sync(0xffffffffu, s0, o);
        s1 += __shfl_xor_sync(0xffffffffu, s1, o);
        s2 += __shfl_xor_sync(0xffffffffu, s2, o);
        s3 += __shfl_xor_sync(0xffffffffu, s3, o);
    }

    if (lane < 4) {
        const float sv = (lane == 0) ? s0 : (lane == 1) ? s1 : (lane == 2) ? s2 : s3;
        rowscores[lane * BATCH + b] = sv;
    }

    const float mx = fmaxf(fmaxf(s0, s1), fmaxf(s2, s3));
    const float e0 = expf(s0 - mx), e1 = expf(s1 - mx);
    const float e2 = expf(s2 - mx), e3 = expf(s3 - mx);
    const float inv = 1.f / (e0 + e1 + e2 + e3);
    const float w0 = e0 * inv, w1 = e1 * inv, w2 = e2 * inv, w3 = e3 * inv;

#pragma unroll
    for (int g = 0; g < 2; g++) {
        const int j = g * 128 + lane * 4;
        float o[4];
#pragma unroll
        for (int q = 0; q < 4; q++)
            o[q] = w0 * c[g][0][q] + w1 * c[g][1][q] + w2 * c[g][2][q] + w3 * c[g][3][q];

        float* op = out1 + (size_t)b * ldo1 + j;
        op[0] = o[0]; op[1] = o[1]; op[2] = o[2]; op[3] = o[3];
        if (out2)
            *(float4*)(out2 + (size_t)b * HID + j) = make_float4(o[0], o[1], o[2], o[3]);
        if (obh) {
            __nv_bfloat16 hh[4], ll[4];
#pragma unroll
            for (int q = 0; q < 4; q++) {
                hh[q] = __float2bfloat16(o[q]);
                ll[q] = __float2bfloat16(o[q] - __bfloat162float(hh[q]));
            }
            __nv_bfloat162* ph = (__nv_bfloat162*)(obh + (size_t)b * HID + j);
            __nv_bfloat162* pl = (__nv_bfloat162*)(obl + (size_t)b * HID + j);
            ph[0] = __nv_bfloat162{hh[0], hh[1]};
            ph[1] = __nv_bfloat162{hh[2], hh[3]};
            pl[0] = __nv_bfloat162{ll[0], ll[1]};
            pl[1] = __nv_bfloat162{ll[2], ll[3]};
        }
    }
}

// ---------------- finalize ----------------
__global__ __launch_bounds__(256)
void fin_sum(const float* __restrict__ rs)
{
    __shared__ double tmp[256];
    const int idx = blockIdx.x;
    const int tid = threadIdx.x;
    double p = 0.0;
    for (int i = tid; i < BATCH; i += 256) p += (double)rs[idx * BATCH + i];
    tmp[tid] = p;
    __syncthreads();
    for (int o = 128; o > 0; o >>= 1) {
        if (tid < o) tmp[tid] += tmp[tid + o];
        __syncthreads();
    }
    if (tid == 0) g_ssum[idx] = tmp[0];
}

__global__ void fin_out(float* __restrict__ out)
{
    if (threadIdx.x == 0) {
        out[OFF_GS + 0] = 0.f;
        out[OFF_GS + 1] = 1.f;
        out[OFF_GS + 2] = 0.f;
        for (int s = 0; s < 6; s++) {
            double best = g_ssum[s * 4]; int bi = 0;
            for (int k = 1; k < 4; k++)
                if (g_ssum[s * 4 + k] > best) { best = g_ssum[s * 4 + k]; bi = k; }
            double second = -1e300;
            for (int k = 0; k < 4; k++)
                if (k != bi && g_ssum[s * 4 + k] > second) second = g_ssum[s * 4 + k];
            out[OFF_GS + 3 + s] = (float)bi;
            out[OFF_MARG + s]   = (float)(best - second);
        }
    }
}

// ---------------- launcher ----------------
extern "C" void kernel_launch(void* const* d_in, const int* in_sizes, int n_in,
                              void* d_out, int out_size)
{
    const float* x  = (const float*)d_in[0];
    const float* h  = (const float*)d_in[1];
    const float* L  = (const float*)d_in[2];
    const float* R  = (const float*)d_in[3];
    const float* bb = (const float*)d_in[4];
    const float* Ws = (const float*)d_in[5];
    float* out = (float*)d_out;

    static bool attr_done = false;
    if (!attr_done) {
        cudaFuncSetAttribute(tc_gemm, cudaFuncAttributeMaxDynamicSharedMemorySize, DYN_SMEM);
        attr_done = true;
    }

    float *p_hL, *p_tmp, *p_cand, *p_rows;
    __nv_bfloat16 *p_bf, *p_w;
    cudaGetSymbolAddress((void**)&p_hL,   g_hL);
    cudaGetSymbolAddress((void**)&p_tmp,  g_tmp);
    cudaGetSymbolAddress((void**)&p_cand, g_cand);
    cudaGetSymbolAddress((void**)&p_rows, g_rows);
    cudaGetSymbolAddress((void**)&p_bf,   g_bf);
    cudaGetSymbolAddress((void**)&p_w,    g_w);

    __nv_bfloat16* xh   = p_bf + 0ull  * UNIT;
    __nv_bfloat16* xl   = p_bf + 1ull  * UNIT;
    __nv_bfloat16* hh   = p_bf + 2ull  * UNIT;
    __nv_bfloat16* hl   = p_bf + 3ull  * UNIT;
    __nv_bfloat16* z1rh = p_bf + 4ull  * UNIT;   // 2 units, ld 512
    __nv_bfloat16* z1rl = p_bf + 6ull  * UNIT;
    __nv_bfloat16* rhh  = p_bf + 8ull  * UNIT;
    __nv_bfloat16* rhl  = p_bf + 9ull  * UNIT;
    __nv_bfloat16* hth  = p_bf + 10ull * UNIT;
    __nv_bfloat16* htl  = p_bf + 11ull * UNIT;
    __nv_bfloat16* omh  = p_bf + 12ull * UNIT;
    __nv_bfloat16* oml  = p_bf + 13ull * UNIT;
    __nv_bfloat16* zth  = p_bf + 14ull * UNIT;
    __nv_bfloat16* ztl  = p_bf + 15ull * UNIT;
    __nv_bfloat16* z2hh = p_bf + 16ull * UNIT;
    __nv_bfloat16* z2hl = p_bf + 17ull * UNIT;

    __nv_bfloat16* Lh = p_w + 0ull * WUNIT;
    __nv_bfloat16* Ll = p_w + 1ull * WUNIT;
    __nv_bfloat16* Rh = p_w + 2ull * WUNIT;
    __nv_bfloat16* Rl = p_w + 3ull * WUNIT;

    float* gnode = out + OFF_GNODE;
    const float* b3 = bb + 768;
    const dim3 blk(256);
    const dim3 gW(8, 8, 8);
    const dim3 g512(4, BATCH / 128);
    const dim3 g768(6, BATCH / 128);
    const dim3 gmix(BATCH / 8);
    const __nv_bfloat16* NB = (const __nv_bfloat16*)0;
    const float* NF = (const float*)0;
    __nv_bfloat16* NBo = (__nv_bfloat16*)0;

    prep_weights<<<gW, blk>>>(L, R, Lh, Ll, Rh, Rl);
    conv_split2<<<2 * BATCH * HID / 256, blk>>>(x, h, xh, xl, hh, hl);

    // stage 0: [z1 | r] = sig(x@L + h@R + b), cols 0..511; also dup z2=z1 into slot2
    tc_gemm<<<g512, blk, DYN_SMEM>>>(xh, xl, 256, Lh, Ll, hh, hl, 256, Rh, Rl, 2,
                                     bb, NF, 0,
                                     gnode, GROW, EPI_SIG,
                                     NF, 0, (float*)0, 0, 0,
                                     z1rh, z1rl, 512, 1);

    // hL = h @ L[0..2]  (768 cols, no bias)
    tc_gemm<<<g768, blk, DYN_SMEM>>>(hh, hl, 256, Lh, Ll, NB, NB, 0, NB, NB, 1,
                                     NF, NF, 0,
                                     p_hL, 768, EPI_NONE,
                                     NF, 0, (float*)0, 0, 0,
                                     NBo, NBo, 0, 0);

    // CE: v = z1@R ; cand_C = 1-(v+b) -> g_cand ; cand_E = v*hL + b -> g_tmp
    tc_gemm<<<g768, blk, DYN_SMEM>>>(z1rh, z1rl, 512, Rh, Rl, NB, NB, 0, NB, NB, 1,
                                     bb, NF, 0,
                                     p_cand, 768, EPI_OMZ,
                                     p_hL, 768, p_tmp, 768, EPI_MUL,
                                     NBo, NBo, 0, 0);
    // mixC: oneMinusZ1 -> slot 5 ; c3 = 1 - (z1 + b3)
    mixture_kernel<<<gmix, blk>>>(p_cand, 768, gnode + 0 * HID, GROW, NF, 0, C3_OMZ,
                                  b3, Ws, gnode + 5 * HID, GROW, (float*)0,
                                  omh, oml, p_rows + 2 * 4 * BATCH);
    // mixE: z2h -> slot 7 ; c3 = h * z1 + b3
    mixture_kernel<<<gmix, blk>>>(p_tmp, 768, h, HID, gnode + 0 * HID, GROW, C3_MUL,
                                  b3, Ws, gnode + 7 * HID, GROW, (float*)0,
                                  z2hh, z2hl, p_rows + 4 * 4 * BATCH);

    // stage A: cand = r@R + hL + b -> g_cand ; rh -> slot 3 ; c3 = h + r + b3
    tc_gemm<<<g768, blk, DYN_SMEM>>>(z1rh + 256, z1rl + 256, 512, Rh, Rl, NB, NB, 0, NB, NB, 1,
                                     bb, p_hL, 768,
                                     p_cand, 768, EPI_ADD,
                                     NF, 0, (float*)0, 0, 0,
                                     NBo, NBo, 0, 0);
    mixture_kernel<<<gmix, blk>>>(p_cand, 768, h, HID, gnode + 1 * HID, GROW, C3_ADD,
                                  b3, Ws, gnode + 3 * HID, GROW, (float*)0,
                                  rhh, rhl, p_rows + 0 * 4 * BATCH);

    // stage B: cand = x@L + rh@R + b ; h_tilde -> slot 4 ; c3 = x + rh + b3
    tc_gemm<<<g768, blk, DYN_SMEM>>>(xh, xl, 256, Lh, Ll, rhh, rhl, 256, Rh, Rl, 2,
                                     bb, NF, 0,
                                     p_cand, 768, EPI_NONE,
                                     NF, 0, (float*)0, 0, 0,
                                     NBo, NBo, 0, 0);
    mixture_kernel<<<gmix, blk>>>(p_cand, 768, x, HID, gnode + 3 * HID, GROW, C3_ADD,
                                  b3, Ws, gnode + 4 * HID, GROW, (float*)0,
                                  hth, htl, p_rows + 1 * 4 * BATCH);

    // stage D: tmp = ht@L ; cand = (omz@R)*tmp + b ; zh_tilde -> slot 6 ; c3 = ht*omz + b3
    tc_gemm<<<g768, blk, DYN_SMEM>>>(hth, htl, 256, Lh, Ll, NB, NB, 0, NB, NB, 1,
                                     NF, NF, 0,
                                     p_tmp, 768, EPI_NONE,
                                     NF, 0, (float*)0, 0, 0,
                                     NBo, NBo, 0, 0);
    tc_gemm<<<g768, blk, DYN_SMEM>>>(omh, oml, 256, Rh, Rl, NB, NB, 0, NB, NB, 1,
                                     bb, p_tmp, 768,
                                     p_cand, 768, EPI_MUL,
                                     NF, 0, (float*)0, 0, 0,
                                     NBo, NBo, 0, 0);
    mixture_kernel<<<gmix, blk>>>(p_cand, 768, gnode + 4 * HID, GROW, gnode + 5 * HID, GROW, C3_MUL,
                                  b3, Ws, gnode + 6 * HID, GROW, (float*)0,
                                  zth, ztl, p_rows + 3 * 4 * BATCH);

    // stage F: cand = zt@L + z2h@R + b ; h_next -> slot 8 + output ; c3 = zt + z2h + b3
    tc_gemm<<<g768, blk, DYN_SMEM>>>(zth, ztl, 256, Lh, Ll, z2hh, z2hl, 256, Rh, Rl, 2,
                                     bb, NF, 0,
                                     p_cand, 768, EPI_NONE,
                                     NF, 0, (float*)0, 0, 0,
                                     NBo, NBo, 0, 0);
    mixture_kernel<<<gmix, blk>>>(p_cand, 768, gnode + 6 * HID, GROW, gnode + 7 * HID, GROW, C3_ADD,
                                  b3, Ws, gnode + 8 * HID, GROW, out + OFF_HNEXT,
                                  NBo, NBo, p_rows + 5 * 4 * BATCH);

    fin_sum<<<24, blk>>>(p_rows);
    fin_out<<<1, 32>>>(out);
}

// round 6
// speedup vs baseline: 3.7591x; 1.0651x over previous
#include <cuda_runtime.h>
#include <cuda_bf16.h>
#include <math.h>
#include <stdint.h>

// ---------------- problem constants ----------------
#define BATCH 16384
#define HID   256

#define OFF_HNEXT 0
#define OFF_GS    (BATCH * HID)
#define OFF_GNODE (OFF_GS + 9)
#define OFF_MARG  (OFF_GNODE + BATCH * 9 * HID)
#define GROW      (9 * HID)

#define EPI_NONE 0
#define EPI_SIG  1
#define EPI_ADD  2
#define EPI_MUL  3
#define EPI_OMZ  4

#define C3_ADD 0
#define C3_OMZ 1
#define C3_MUL 2

// ---------------- scratch ----------------
__device__ float g_hL[BATCH * 768];
__device__ float g_tmp[BATCH * 768];
__device__ float g_cand[BATCH * 768];
__device__ float g_cand2[BATCH * 768];
__device__ float g_rows[6 * 4 * BATCH];
__device__ double g_ssum[24];

#define UNIT (BATCH * HID)
__device__ __nv_bfloat16 g_bf[18ull * UNIT];
#define WUNIT (4 * 256 * 256)
__device__ __nv_bfloat16 g_w[4 * WUNIT];

// ---------------- helpers ----------------
__device__ __forceinline__ uint32_t smem_u32(const void* p) {
    uint32_t a;
    asm("{ .reg .u64 t; cvta.to.shared.u64 t, %1; cvt.u32.u64 %0, t; }" : "=r"(a) : "l"(p));
    return a;
}
#define CP16(saddr, gaddr) \
    asm volatile("cp.async.ca.shared.global [%0], [%1], 16;" :: "r"(saddr), "l"(gaddr))
#define CP_COMMIT() asm volatile("cp.async.commit_group;")
#define CP_WAIT1()  asm volatile("cp.async.wait_group 1;")
#define CP_WAIT0()  asm volatile("cp.async.wait_group 0;")

__device__ __forceinline__ void ldm_x4(uint32_t* r, uint32_t addr) {
    asm volatile("ldmatrix.sync.aligned.m8n8.x4.shared.b16 {%0,%1,%2,%3}, [%4];"
                 : "=r"(r[0]), "=r"(r[1]), "=r"(r[2]), "=r"(r[3]) : "r"(addr));
}
__device__ __forceinline__ void ldm_x2(uint32_t* r, uint32_t addr) {
    asm volatile("ldmatrix.sync.aligned.m8n8.x2.shared.b16 {%0,%1}, [%2];"
                 : "=r"(r[0]), "=r"(r[1]) : "r"(addr));
}
__device__ __forceinline__ void mma_bf16(float* d, const uint32_t* a, const uint32_t* b) {
    asm volatile(
        "mma.sync.aligned.m16n8k16.row.col.f32.bf16.bf16.f32 "
        "{%0,%1,%2,%3}, {%4,%5,%6,%7}, {%8,%9}, {%0,%1,%2,%3};"
        : "+f"(d[0]), "+f"(d[1]), "+f"(d[2]), "+f"(d[3])
        : "r"(a[0]), "r"(a[1]), "r"(a[2]), "r"(a[3]), "r"(b[0]), "r"(b[1]));
}

// ---------------- GEMM job ----------------
struct GJob {
    const __nv_bfloat16 *A1h, *A1l, *A2h, *A2l;
    const __nv_bfloat16 *W1h, *W1l, *W2h, *W2l;
    const float *bias, *Dop, *D2op;
    float *C, *C2;
    __nv_bfloat16 *Obh, *Obl;
    int lda1, lda2, nPair, ldd, ldc, mode, ldd2, ldc2, mode2, ldob, dupz2;
};

// tile 128x64, warp 32x32, 8 warps, 2-stage cp.async
// stage: Ah(128x40) Al Bh(64x40) Bl  = 30720 B
#define LDS 40
#define A_T_B (128 * LDS * 2)     // 10240
#define B_T_B (64 * LDS * 2)      // 5120
#define STAGE_B (2 * A_T_B + 2 * B_T_B)   // 30720
#define DYN_SMEM (2 * STAGE_B)            // 61440

__device__ __forceinline__ void gemm_body(const GJob& J, int xt, char* smc, uint32_t smb)
{
    const int tid  = threadIdx.x;
    const int wid  = tid >> 5;
    const int lane = tid & 31;

    const int row0   = blockIdx.y * 128;
    const int n0     = xt * 64;
    const int kslice = n0 >> 8;
    const int wc0    = n0 & 255;

    const __nv_bfloat16* wBh1 = J.W1h + kslice * 65536;
    const __nv_bfloat16* wBl1 = J.W1l + kslice * 65536;
    const __nv_bfloat16* wBh2 = J.W2h ? J.W2h + kslice * 65536 : (const __nv_bfloat16*)0;
    const __nv_bfloat16* wBl2 = J.W2l ? J.W2l + kslice * 65536 : (const __nv_bfloat16*)0;

    const int NCH = J.nPair * 8;

    const int lrowA = tid >> 1;
    const int lkofA = (tid & 1) * 16;
    const int lrowB = tid >> 2;
    const int lkofB = (tid & 3) * 8;

    float acc[32];
#pragma unroll
    for (int i = 0; i < 32; i++) acc[i] = 0.f;

    const int wm = (wid >> 1) * 32;
    const int wn = (wid & 1) * 32;

    auto load_chunk = [&](int c, int buf) {
        const __nv_bfloat16 *pAh, *pAl, *pWh, *pWl;
        int lda;
        if (c < 8) { pAh = J.A1h; pAl = J.A1l; lda = J.lda1; pWh = wBh1; pWl = wBl1; }
        else       { pAh = J.A2h; pAl = J.A2l; lda = J.lda2; pWh = wBh2; pWl = wBl2; }
        const int k0 = (c & 7) * 32;
        const uint32_t sb = smb + buf * STAGE_B;
        const uint32_t soA = (lrowA * LDS + lkofA) * 2;
        const __nv_bfloat16* gA = pAh + (size_t)(row0 + lrowA) * lda + k0 + lkofA;
        CP16(sb + soA,      gA);
        CP16(sb + soA + 16, gA + 8);
        const __nv_bfloat16* gAl = pAl + (size_t)(row0 + lrowA) * lda + k0 + lkofA;
        CP16(sb + A_T_B + soA,      gAl);
        CP16(sb + A_T_B + soA + 16, gAl + 8);
        const uint32_t soB = (lrowB * LDS + lkofB) * 2;
        CP16(sb + 2 * A_T_B + soB,         pWh + (size_t)(wc0 + lrowB) * 256 + k0 + lkofB);
        CP16(sb + 2 * A_T_B + B_T_B + soB, pWl + (size_t)(wc0 + lrowB) * 256 + k0 + lkofB);
        CP_COMMIT();
    };

    load_chunk(0, 0);

    const uint32_t aRow = (uint32_t)(wm + (lane & 15));
    const uint32_t aKh  = (uint32_t)((lane >> 4) * 8);
    const uint32_t bRow = (uint32_t)(wn + (lane & 7));
    const uint32_t bKh  = (uint32_t)(((lane >> 3) & 1) * 8);

    for (int c = 0; c < NCH; c++) {
        if (c + 1 < NCH) { load_chunk(c + 1, (c + 1) & 1); CP_WAIT1(); }
        else             { CP_WAIT0(); }
        __syncthreads();

        const uint32_t sb = smb + (c & 1) * STAGE_B;
#pragma unroll
        for (int ks = 0; ks < 2; ks++) {
            uint32_t ah[2][4], al[2][4];
#pragma unroll
            for (int i = 0; i < 2; i++) {
                const uint32_t off = ((aRow + i * 16) * LDS + ks * 16 + aKh) * 2;
                ldm_x4(ah[i], sb + off);
                ldm_x4(al[i], sb + A_T_B + off);
            }
#pragma unroll
            for (int j = 0; j < 4; j++) {
                uint32_t bh[2], bl[2];
                const uint32_t off = ((bRow + j * 8) * LDS + ks * 16 + bKh) * 2;
                ldm_x2(bh, sb + 2 * A_T_B + off);
                ldm_x2(bl, sb + 2 * A_T_B + B_T_B + off);
#pragma unroll
                for (int i = 0; i < 2; i++) {
                    float* d = &acc[(i * 4 + j) * 4];
                    mma_bf16(d, ah[i], bh);
                    mma_bf16(d, ah[i], bl);
                    mma_bf16(d, al[i], bh);
                }
            }
        }
        __syncthreads();
    }

    // epilogue: regs -> smem (128 x 68 f32) -> gmem
    float* smf = (float*)smc;
    {
        const int r0 = lane >> 2;
        const int cc = (lane & 3) * 2;
#pragma unroll
        for (int i = 0; i < 2; i++)
#pragma unroll
            for (int j = 0; j < 4; j++) {
                const float* d = &acc[(i * 4 + j) * 4];
                const int rr = wm + i * 16 + r0;
                const int col = wn + j * 8 + cc;
                smf[rr * 68 + col]           = d[0];
                smf[rr * 68 + col + 1]       = d[1];
                smf[(rr + 8) * 68 + col]     = d[2];
                smf[(rr + 8) * 68 + col + 1] = d[3];
            }
    }
    __syncthreads();

    const bool c_vec  = ((((uintptr_t)J.C) & 15) == 0) && ((J.ldc & 3) == 0);
    const bool c2_vec = J.C2 && ((((uintptr_t)J.C2) & 15) == 0) && ((J.ldc2 & 3) == 0);

#pragma unroll
    for (int it = 0; it < 8; it++) {
        const int f4 = it * 256 + tid;
        const int rr = f4 >> 4;
        const int c4 = (f4 & 15) * 4;
        float4 v = *(float4*)&smf[rr * 68 + c4];
        const int row = row0 + rr;
        const int gn  = n0 + c4;
        float o[4];
        float dv[4] = {0.f, 0.f, 0.f, 0.f};
        if (J.mode == EPI_ADD || J.mode == EPI_MUL) {
            float4 d4 = *(const float4*)(J.Dop + (size_t)row * J.ldd + gn);
            dv[0] = d4.x; dv[1] = d4.y; dv[2] = d4.z; dv[3] = d4.w;
        }
#pragma unroll
        for (int q = 0; q < 4; q++) {
            const float val = (&v.x)[q];
            const float bv = J.bias ? J.bias[gn + q] : 0.f;
            float res;
            if (J.mode == EPI_SIG)      res = 1.f / (1.f + expf(-(val + bv)));
            else if (J.mode == EPI_ADD) res = val + dv[q] + bv;
            else if (J.mode == EPI_MUL) res = val * dv[q] + bv;
            else if (J.mode == EPI_OMZ) res = 1.f - (val + bv);
            else                        res = val + bv;
            o[q] = res;
        }
        float* cp = J.C + (size_t)row * J.ldc + gn;
        if (c_vec) *(float4*)cp = make_float4(o[0], o[1], o[2], o[3]);
        else { cp[0] = o[0]; cp[1] = o[1]; cp[2] = o[2]; cp[3] = o[3]; }

        if (J.dupz2 && gn < 256) {
            float* zp = J.C + (size_t)row * J.ldc + 512 + gn;
            zp[0] = o[0]; zp[1] = o[1]; zp[2] = o[2]; zp[3] = o[3];
        }

        if (J.C2) {
            float o2[4];
            float dv2[4] = {0.f, 0.f, 0.f, 0.f};
            if (J.mode2 == EPI_ADD || J.mode2 == EPI_MUL) {
                float4 d4 = *(const float4*)(J.D2op + (size_t)row * J.ldd2 + gn);
                dv2[0] = d4.x; dv2[1] = d4.y; dv2[2] = d4.z; dv2[3] = d4.w;
            }
#pragma unroll
            for (int q = 0; q < 4; q++) {
                const float val = (&v.x)[q];
                const float bv = J.bias ? J.bias[gn + q] : 0.f;
                float res;
                if (J.mode2 == EPI_SIG)      res = 1.f / (1.f + expf(-(val + bv)));
                else if (J.mode2 == EPI_ADD) res = val + dv2[q] + bv;
                else if (J.mode2 == EPI_MUL) res = val * dv2[q] + bv;
                else if (J.mode2 == EPI_OMZ) res = 1.f - (val + bv);
                else                         res = val + bv;
                o2[q] = res;
            }
            float* cp2 = J.C2 + (size_t)row * J.ldc2 + gn;
            if (c2_vec) *(float4*)cp2 = make_float4(o2[0], o2[1], o2[2], o2[3]);
            else { cp2[0] = o2[0]; cp2[1] = o2[1]; cp2[2] = o2[2]; cp2[3] = o2[3]; }
        }

        if (J.Obh) {
            __nv_bfloat16 hh[4], ll[4];
#pragma unroll
            for (int q = 0; q < 4; q++) {
                hh[q] = __float2bfloat16(o[q]);
                ll[q] = __float2bfloat16(o[q] - __bfloat162float(hh[q]));
            }
            __nv_bfloat162* ph = (__nv_bfloat162*)(J.Obh + (size_t)row * J.ldob + gn);
            __nv_bfloat162* pl = (__nv_bfloat162*)(J.Obl + (size_t)row * J.ldob + gn);
            ph[0] = __nv_bfloat162{hh[0], hh[1]};
            ph[1] = __nv_bfloat162{hh[2], hh[3]};
            pl[0] = __nv_bfloat162{ll[0], ll[1]};
            pl[1] = __nv_bfloat162{ll[2], ll[3]};
        }
    }
}

__global__ __launch_bounds__(256, 3)
void tc_gemm2(GJob j0, GJob j1, int nx0)
{
    extern __shared__ char smc[];
    const uint32_t smb = smem_u32(smc);
    if ((int)blockIdx.x < nx0) gemm_body(j0, blockIdx.x, smc, smb);
    else                       gemm_body(j1, blockIdx.x - nx0, smc, smb);
}

// ---------------- prep: weights transpose+split AND input split ----------
__global__ __launch_bounds__(256)
void prep_all(const float* __restrict__ L, const float* __restrict__ R,
              const float* __restrict__ x, const float* __restrict__ h,
              __nv_bfloat16* __restrict__ Lh, __nv_bfloat16* __restrict__ Ll,
              __nv_bfloat16* __restrict__ Rh, __nv_bfloat16* __restrict__ Rl,
              __nv_bfloat16* __restrict__ xh, __nv_bfloat16* __restrict__ xl,
              __nv_bfloat16* __restrict__ hh, __nv_bfloat16* __restrict__ hl)
{
    __shared__ float t[32][33];
    const int bid = blockIdx.x;
    if (bid < 512) {
        const int mz = bid >> 6;
        const int rem = bid & 63;
        const int h0 = (rem >> 3) * 32, d0 = (rem & 7) * 32;
        const float* src = (mz < 4) ? L : R;
        __nv_bfloat16* dh = (mz < 4) ? Lh : Rh;
        __nv_bfloat16* dl = (mz < 4) ? Ll : Rl;
        const int k = mz & 3;
        const int tx = threadIdx.x & 31, ty = threadIdx.x >> 5;
        for (int i = 0; i < 32; i += 8)
            t[ty + i][tx] = src[k * 65536 + (h0 + ty + i) * 256 + d0 + tx];
        __syncthreads();
        for (int i = 0; i < 32; i += 8) {
            const float v = t[tx][ty + i];
            const __nv_bfloat16 hi = __float2bfloat16(v);
            const __nv_bfloat16 lo = __float2bfloat16(v - __bfloat162float(hi));
            dh[k * 65536 + (d0 + ty + i) * 256 + h0 + tx] = hi;
            dl[k * 65536 + (d0 + ty + i) * 256 + h0 + tx] = lo;
        }
    } else {
        const int i = (bid - 512) * 256 + threadIdx.x;
        const int n = BATCH * HID;
        const float v = (i < n) ? x[i] : h[i - n];
        __nv_bfloat16* dh = (i < n) ? xh : hh;
        __nv_bfloat16* dl = (i < n) ? xl : hl;
        const int idx = (i < n) ? i : i - n;
        const __nv_bfloat16 hi = __float2bfloat16(v);
        dh[idx] = hi;
        dl[idx] = __float2bfloat16(v - __bfloat162float(hi));
    }
}

// ---------------- mixture (multi-job) ----------------
struct MJob {
    const float *cand, *P, *Q;
    float *out1, *out2;
    __nv_bfloat16 *obh, *obl;
    float *rows;
    int ldcand, ldp, ldq, c3mode, ldo1;
};

__device__ __forceinline__ void mix_body(const MJob& M, int local,
                                         const float* __restrict__ b3,
                                         const float* __restrict__ Ws)
{
    const int warp = threadIdx.x >> 5;
    const int lane = threadIdx.x & 31;
    const int b = local * 8 + warp;

    const float* cr = M.cand + (size_t)b * M.ldcand;
    const float* pr = M.P + (size_t)b * M.ldp;
    const float* qr = M.Q ? M.Q + (size_t)b * M.ldq : (const float*)0;

    float c[2][4][4];
    float s0 = 0.f, s1 = 0.f, s2 = 0.f, s3 = 0.f;

#pragma unroll
    for (int g = 0; g < 2; g++) {
        const int j = g * 128 + lane * 4;
        float4 v0 = *(const float4*)(cr + j);
        float4 v1 = *(const float4*)(cr + 256 + j);
        float4 v2 = *(const float4*)(cr + 512 + j);
        float4 bw = *(const float4*)(b3 + j);
        float4 wv = *(const float4*)(Ws + j);
        float p0 = pr[j], p1 = pr[j + 1], p2 = pr[j + 2], p3 = pr[j + 3];
        float c3v[4];
        if (M.c3mode == C3_ADD) {
            c3v[0] = p0 + qr[j]     + bw.x;
            c3v[1] = p1 + qr[j + 1] + bw.y;
            c3v[2] = p2 + qr[j + 2] + bw.z;
            c3v[3] = p3 + qr[j + 3] + bw.w;
        } else if (M.c3mode == C3_OMZ) {
            c3v[0] = 1.f - (p0 + bw.x);
            c3v[1] = 1.f - (p1 + bw.y);
            c3v[2] = 1.f - (p2 + bw.z);
            c3v[3] = 1.f - (p3 + bw.w);
        } else {
            c3v[0] = p0 * qr[j]     + bw.x;
            c3v[1] = p1 * qr[j + 1] + bw.y;
            c3v[2] = p2 * qr[j + 2] + bw.z;
            c3v[3] = p3 * qr[j + 3] + bw.w;
        }
        c[g][0][0] = v0.x; c[g][0][1] = v0.y; c[g][0][2] = v0.z; c[g][0][3] = v0.w;
        c[g][1][0] = v1.x; c[g][1][1] = v1.y; c[g][1][2] = v1.z; c[g][1][3] = v1.w;
        c[g][2][0] = v2.x; c[g][2][1] = v2.y; c[g][2][2] = v2.z; c[g][2][3] = v2.w;
        c[g][3][0] = c3v[0]; c[g][3][1] = c3v[1]; c[g][3][2] = c3v[2]; c[g][3][3] = c3v[3];
        const float w0 = wv.x, w1 = wv.y, w2 = wv.z, w3 = wv.w;
        s0 += v0.x * w0 + v0.y * w1 + v0.z * w2 + v0.w * w3;
        s1 += v1.x * w0 + v1.y * w1 + v1.z * w2 + v1.w * w3;
        s2 += v2.x * w0 + v2.y * w1 + v2.z * w2 + v2.w * w3;
        s3 += c3v[0] * w0 + c3v[1] * w1 + c3v[2] * w2 + c3v[3] * w3;
    }

#pragma unroll
    for (int o = 16; o > 0; o >>= 1) {
        s0 += __shfl_xor_sync(0xffffffffu, s0, o);
        s1 += __shfl_xor_sync(0xffffffffu, s1, o);
        s2 += __shfl_xor_sync(0xffffffffu, s2, o);
        s3 += __shfl_xor_sync(0xffffffffu, s3, o);
    }

    if (lane < 4) {
        const float sv = (lane == 0) ? s0 : (lane == 1) ? s1 : (lane == 2) ? s2 : s3;
        M.rows[lane * BATCH + b] = sv;
    }

    const float mx = fmaxf(fmaxf(s0, s1), fmaxf(s2, s3));
    const float e0 = expf(s0 - mx), e1 = expf(s1 - mx);
    const float e2 = expf(s2 - mx), e3 = expf(s3 - mx);
    const float inv = 1.f / (e0 + e1 + e2 + e3);
    const float w0 = e0 * inv, w1 = e1 * inv, w2 = e2 * inv, w3 = e3 * inv;

#pragma unroll
    for (int g = 0; g < 2; g++) {
        const int j = g * 128 + lane * 4;
        float o[4];
#pragma unroll
        for (int q = 0; q < 4; q++)
            o[q] = w0 * c[g][0][q] + w1 * c[g][1][q] + w2 * c[g][2][q] + w3 * c[g][3][q];

        float* op = M.out1 + (size_t)b * M.ldo1 + j;
        op[0] = o[0]; op[1] = o[1]; op[2] = o[2]; op[3] = o[3];
        if (M.out2)
            *(float4*)(M.out2 + (size_t)b * HID + j) = make_float4(o[0], o[1], o[2], o[3]);
        if (M.obh) {
            __nv_bfloat16 hh[4], ll[4];
#pragma unroll
            for (int q = 0; q < 4; q++) {
                hh[q] = __float2bfloat16(o[q]);
                ll[q] = __float2bfloat16(o[q] - __bfloat162float(hh[q]));
            }
            __nv_bfloat162* ph = (__nv_bfloat162*)(M.obh + (size_t)b * HID + j);
            __nv_bfloat162* pl = (__nv_bfloat162*)(M.obl + (size_t)b * HID + j);
            ph[0] = __nv_bfloat162{hh[0], hh[1]};
            ph[1] = __nv_bfloat162{hh[2], hh[3]};
            pl[0] = __nv_bfloat162{ll[0], ll[1]};
            pl[1] = __nv_bfloat162{ll[2], ll[3]};
        }
    }
}

__global__ __launch_bounds__(256)
void mix3(MJob m0, MJob m1, MJob m2, const float* b3, const float* Ws)
{
    const int jid = blockIdx.x >> 11;
    const int local = blockIdx.x & 2047;
    if (jid == 0)      mix_body(m0, local, b3, Ws);
    else if (jid == 1) mix_body(m1, local, b3, Ws);
    else               mix_body(m2, local, b3, Ws);
}

// ---------------- finalize ----------------
__global__ __launch_bounds__(256)
void fin_sum(const float* __restrict__ rs)
{
    __shared__ double tmp[256];
    const int idx = blockIdx.x;
    const int tid = threadIdx.x;
    double p = 0.0;
    for (int i = tid; i < BATCH; i += 256) p += (double)rs[idx * BATCH + i];
    tmp[tid] = p;
    __syncthreads();
    for (int o = 128; o > 0; o >>= 1) {
        if (tid < o) tmp[tid] += tmp[tid + o];
        __syncthreads();
    }
    if (tid == 0) g_ssum[idx] = tmp[0];
}

__global__ void fin_out(float* __restrict__ out)
{
    if (threadIdx.x == 0) {
        out[OFF_GS + 0] = 0.f;
        out[OFF_GS + 1] = 1.f;
        out[OFF_GS + 2] = 0.f;
        for (int s = 0; s < 6; s++) {
            double best = g_ssum[s * 4]; int bi = 0;
            for (int k = 1; k < 4; k++)
                if (g_ssum[s * 4 + k] > best) { best = g_ssum[s * 4 + k]; bi = k; }
            double second = -1e300;
            for (int k = 0; k < 4; k++)
                if (k != bi && g_ssum[s * 4 + k] > second) second = g_ssum[s * 4 + k];
            out[OFF_GS + 3 + s] = (float)bi;
            out[OFF_MARG + s]   = (float)(best - second);
        }
    }
}

// ---------------- launcher ----------------
extern "C" void kernel_launch(void* const* d_in, const int* in_sizes, int n_in,
                              void* d_out, int out_size)
{
    const float* x  = (const float*)d_in[0];
    const float* h  = (const float*)d_in[1];
    const float* L  = (const float*)d_in[2];
    const float* R  = (const float*)d_in[3];
    const float* bb = (const float*)d_in[4];
    const float* Ws = (const float*)d_in[5];
    float* out = (float*)d_out;

    static bool attr_done = false;
    if (!attr_done) {
        cudaFuncSetAttribute(tc_gemm2, cudaFuncAttributeMaxDynamicSharedMemorySize, DYN_SMEM);
        attr_done = true;
    }

    float *p_hL, *p_tmp, *p_cand, *p_cand2, *p_rows;
    __nv_bfloat16 *p_bf, *p_w;
    cudaGetSymbolAddress((void**)&p_hL,    g_hL);
    cudaGetSymbolAddress((void**)&p_tmp,   g_tmp);
    cudaGetSymbolAddress((void**)&p_cand,  g_cand);
    cudaGetSymbolAddress((void**)&p_cand2, g_cand2);
    cudaGetSymbolAddress((void**)&p_rows,  g_rows);
    cudaGetSymbolAddress((void**)&p_bf,    g_bf);
    cudaGetSymbolAddress((void**)&p_w,     g_w);

    __nv_bfloat16* xh   = p_bf + 0ull  * UNIT;
    __nv_bfloat16* xl   = p_bf + 1ull  * UNIT;
    __nv_bfloat16* hh   = p_bf + 2ull  * UNIT;
    __nv_bfloat16* hl   = p_bf + 3ull  * UNIT;
    __nv_bfloat16* z1rh = p_bf + 4ull  * UNIT;
    __nv_bfloat16* z1rl = p_bf + 6ull  * UNIT;
    __nv_bfloat16* rhh  = p_bf + 8ull  * UNIT;
    __nv_bfloat16* rhl  = p_bf + 9ull  * UNIT;
    __nv_bfloat16* hth  = p_bf + 10ull * UNIT;
    __nv_bfloat16* htl  = p_bf + 11ull * UNIT;
    __nv_bfloat16* omh  = p_bf + 12ull * UNIT;
    __nv_bfloat16* oml  = p_bf + 13ull * UNIT;
    __nv_bfloat16* zth  = p_bf + 14ull * UNIT;
    __nv_bfloat16* ztl  = p_bf + 15ull * UNIT;
    __nv_bfloat16* z2hh = p_bf + 16ull * UNIT;
    __nv_bfloat16* z2hl = p_bf + 17ull * UNIT;

    __nv_bfloat16* Lh = p_w + 0ull * WUNIT;
    __nv_bfloat16* Ll = p_w + 1ull * WUNIT;
    __nv_bfloat16* Rh = p_w + 2ull * WUNIT;
    __nv_bfloat16* Rl = p_w + 3ull * WUNIT;

    float* gnode = out + OFF_GNODE;
    const float* b3 = bb + 768;
    const dim3 blk(256);

    // ---- prep
    prep_all<<<512 + 2 * UNIT / 256, blk>>>(L, R, x, h, Lh, Ll, Rh, Rl, xh, xl, hh, hl);

    // ---- GEMM jobs
    GJob jS0{}; // stage0: [z1|r] = sig(x@L + h@R + b), N=512
    jS0.A1h = xh; jS0.A1l = xl; jS0.lda1 = 256; jS0.W1h = Lh; jS0.W1l = Ll;
    jS0.A2h = hh; jS0.A2l = hl; jS0.lda2 = 256; jS0.W2h = Rh; jS0.W2l = Rl;
    jS0.nPair = 2; jS0.bias = bb;
    jS0.C = gnode; jS0.ldc = GROW; jS0.mode = EPI_SIG;
    jS0.Obh = z1rh; jS0.Obl = z1rl; jS0.ldob = 512; jS0.dupz2 = 1;

    GJob jHL{}; // hL = h @ L[0..2], N=768
    jHL.A1h = hh; jHL.A1l = hl; jHL.lda1 = 256; jHL.W1h = Lh; jHL.W1l = Ll;
    jHL.nPair = 1;
    jHL.C = p_hL; jHL.ldc = 768; jHL.mode = EPI_NONE;

    GJob jCE{}; // v = z1@R; cand_C = 1-(v+b) -> g_cand ; cand_E = v*hL + b -> g_tmp
    jCE.A1h = z1rh; jCE.A1l = z1rl; jCE.lda1 = 512; jCE.W1h = Rh; jCE.W1l = Rl;
    jCE.nPair = 1; jCE.bias = bb;
    jCE.C = p_cand; jCE.ldc = 768; jCE.mode = EPI_OMZ;
    jCE.D2op = p_hL; jCE.ldd2 = 768; jCE.C2 = p_tmp; jCE.ldc2 = 768; jCE.mode2 = EPI_MUL;

    GJob jA{};  // cand_A = r@R + hL + b -> g_cand2
    jA.A1h = z1rh + 256; jA.A1l = z1rl + 256; jA.lda1 = 512; jA.W1h = Rh; jA.W1l = Rl;
    jA.nPair = 1; jA.bias = bb;
    jA.Dop = p_hL; jA.ldd = 768;
    jA.C = p_cand2; jA.ldc = 768; jA.mode = EPI_ADD;

    GJob jB{};  // cand_B = x@L + rh@R + b -> g_cand
    jB.A1h = xh; jB.A1l = xl; jB.lda1 = 256; jB.W1h = Lh; jB.W1l = Ll;
    jB.A2h = rhh; jB.A2l = rhl; jB.lda2 = 256; jB.W2h = Rh; jB.W2l = Rl;
    jB.nPair = 2; jB.bias = bb;
    jB.C = p_cand; jB.ldc = 768; jB.mode = EPI_NONE;

    GJob jOR{}; // omzR = omz@R -> g_tmp (no bias)
    jOR.A1h = omh; jOR.A1l = oml; jOR.lda1 = 256; jOR.W1h = Rh; jOR.W1l = Rl;
    jOR.nPair = 1;
    jOR.C = p_tmp; jOR.ldc = 768; jOR.mode = EPI_NONE;

    GJob jD{};  // cand_D = (ht@L) * omzR + b -> g_cand2
    jD.A1h = hth; jD.A1l = htl; jD.lda1 = 256; jD.W1h = Lh; jD.W1l = Ll;
    jD.nPair = 1; jD.bias = bb;
    jD.Dop = p_tmp; jD.ldd = 768;
    jD.C = p_cand2; jD.ldc = 768; jD.mode = EPI_MUL;

    GJob jF{};  // cand_F = zt@L + z2h@R + b -> g_cand
    jF.A1h = zth; jF.A1l = ztl; jF.lda1 = 256; jF.W1h = Lh; jF.W1l = Ll;
    jF.A2h = z2hh; jF.A2l = z2hl; jF.lda2 = 256; jF.W2h = Rh; jF.W2l = Rl;
    jF.nPair = 2; jF.bias = bb;
    jF.C = p_cand; jF.ldc = 768; jF.mode = EPI_NONE;

    // ---- mix jobs
    MJob mC{}; mC.cand = p_cand; mC.ldcand = 768; mC.P = gnode; mC.ldp = GROW;
    mC.c3mode = C3_OMZ; mC.out1 = gnode + 5 * HID; mC.ldo1 = GROW;
    mC.obh = omh; mC.obl = oml; mC.rows = p_rows + 2 * 4 * BATCH;

    MJob mE{}; mE.cand = p_tmp; mE.ldcand = 768; mE.P = h; mE.ldp = HID;
    mE.Q = gnode; mE.ldq = GROW; mE.c3mode = C3_MUL;
    mE.out1 = gnode + 7 * HID; mE.ldo1 = GROW;
    mE.obh = z2hh; mE.obl = z2hl; mE.rows = p_rows + 4 * 4 * BATCH;

    MJob mA{}; mA.cand = p_cand2; mA.ldcand = 768; mA.P = h; mA.ldp = HID;
    mA.Q = gnode + 1 * HID; mA.ldq = GROW; mA.c3mode = C3_ADD;
    mA.out1 = gnode + 3 * HID; mA.ldo1 = GROW;
    mA.obh = rhh; mA.obl = rhl; mA.rows = p_rows + 0 * 4 * BATCH;

    MJob mB{}; mB.cand = p_cand; mB.ldcand = 768; mB.P = x; mB.ldp = HID;
    mB.Q = gnode + 3 * HID; mB.ldq = GROW; mB.c3mode = C3_ADD;
    mB.out1 = gnode + 4 * HID; mB.ldo1 = GROW;
    mB.obh = hth; mB.obl = htl; mB.rows = p_rows + 1 * 4 * BATCH;

    MJob mD{}; mD.cand = p_cand2; mD.ldcand = 768; mD.P = gnode + 4 * HID; mD.ldp = GROW;
    mD.Q = gnode + 5 * HID; mD.ldq = GROW; mD.c3mode = C3_MUL;
    mD.out1 = gnode + 6 * HID; mD.ldo1 = GROW;
    mD.obh = zth; mD.obl = ztl; mD.rows = p_rows + 3 * 4 * BATCH;

    MJob mF{}; mF.cand = p_cand; mF.ldcand = 768; mF.P = gnode + 6 * HID; mF.ldp = GROW;
    mF.Q = gnode + 7 * HID; mF.ldq = GROW; mF.c3mode = C3_ADD;
    mF.out1 = gnode + 8 * HID; mF.ldo1 = GROW; mF.out2 = out + OFF_HNEXT;
    mF.rows = p_rows + 5 * 4 * BATCH;

    const dim3 gRows(1, BATCH / 128);

    // wave 1: stage0 (8 tiles) + hL (12 tiles)
    tc_gemm2<<<dim3(20, BATCH / 128), blk, DYN_SMEM>>>(jS0, jHL, 8);
    // wave 2: CE (12) + A (12)
    tc_gemm2<<<dim3(24, BATCH / 128), blk, DYN_SMEM>>>(jCE, jA, 12);
    // wave 3: mix C, E, A
    mix3<<<3 * 2048, blk>>>(mC, mE, mA, b3, Ws);
    // wave 4: B (12) + omzR (12)
    tc_gemm2<<<dim3(24, BATCH / 128), blk, DYN_SMEM>>>(jB, jOR, 12);
    // wave 5: mix B
    mix3<<<2048, blk>>>(mB, mB, mB, b3, Ws);
    // wave 6: D
    tc_gemm2<<<dim3(12, BATCH / 128), blk, DYN_SMEM>>>(jD, jD, 12);
    // wave 7: mix D
    mix3<<<2048, blk>>>(mD, mD, mD, b3, Ws);
    // wave 8: F
    tc_gemm2<<<dim3(12, BATCH / 128), blk, DYN_SMEM>>>(jF, jF, 12);
    // wave 9: mix F
    mix3<<<2048, blk>>>(mF, mF, mF, b3, Ws);

    fin_sum<<<24, blk>>>(p_rows);
    fin_out<<<1, 32>>>(out);
}

// round 10
// speedup vs baseline: 5.2071x; 1.3852x over previous
#include <cuda_runtime.h>
#include <cuda_fp16.h>
#include <math.h>
#include <stdint.h>

// ---------------- problem constants ----------------
#define BATCH 16384
#define HID   256

#define OFF_HNEXT 0
#define OFF_GS    (BATCH * HID)
#define OFF_GNODE (OFF_GS + 9)
#define OFF_MARG  (OFF_GNODE + BATCH * 9 * HID)
#define GROW      (9 * HID)

#define EPI_NONE 0
#define EPI_SIG  1
#define EPI_ADD  2
#define EPI_MUL  3
#define EPI_OMZ  4

#define C3_ADD 0
#define C3_OMZ 1
#define C3_MUL 2

// ---------------- scratch ----------------
__device__ float g_hL[BATCH * 768];
__device__ float g_tmp[BATCH * 768];
__device__ float g_cand[BATCH * 768];
__device__ float g_cand2[BATCH * 768];
__device__ float g_rows[6 * 4 * BATCH];
__device__ double g_ssum[24];

#define UNIT (BATCH * HID)
// fp16 activations: 0:x 1:h 2,3:z1r(ld512) 4:rh 5:ht 6:om 7:zt 8:z2h
__device__ __half g_hf[9ull * UNIT];
#define WUNIT (4 * 256 * 256)
// fp16 weights K-major [d][h]: Lh, Ll, Rh, Rl
__device__ __half g_wh[4 * WUNIT];

// ---------------- helpers ----------------
__device__ __forceinline__ uint32_t smem_u32(const void* p) {
    uint32_t a;
    asm("{ .reg .u64 t; cvta.to.shared.u64 t, %1; cvt.u32.u64 %0, t; }" : "=r"(a) : "l"(p));
    return a;
}
#define CP16(saddr, gaddr) \
    asm volatile("cp.async.ca.shared.global [%0], [%1], 16;" :: "r"(saddr), "l"(gaddr))
#define CP_COMMIT() asm volatile("cp.async.commit_group;")
#define CP_WAIT1()  asm volatile("cp.async.wait_group 1;")
#define CP_WAIT0()  asm volatile("cp.async.wait_group 0;")

__device__ __forceinline__ void ldm_x4(uint32_t* r, uint32_t addr) {
    asm volatile("ldmatrix.sync.aligned.m8n8.x4.shared.b16 {%0,%1,%2,%3}, [%4];"
                 : "=r"(r[0]), "=r"(r[1]), "=r"(r[2]), "=r"(r[3]) : "r"(addr));
}
__device__ __forceinline__ void mma_f16(float* d, const uint32_t* a, const uint32_t* b) {
    asm volatile(
        "mma.sync.aligned.m16n8k16.row.col.f32.f16.f16.f32 "
        "{%0,%1,%2,%3}, {%4,%5,%6,%7}, {%8,%9}, {%0,%1,%2,%3};"
        : "+f"(d[0]), "+f"(d[1]), "+f"(d[2]), "+f"(d[3])
        : "r"(a[0]), "r"(a[1]), "r"(a[2]), "r"(a[3]), "r"(b[0]), "r"(b[1]));
}

// ---------------- GEMM job ----------------
struct GJob {
    const __half *A1, *A2;
    const __half *W1h, *W1l, *W2h, *W2l;
    const float *bias, *Dop, *D2op;
    float *C, *C2;
    __half *Ob;
    int lda1, lda2, nPair, ldd, ldc, mode, ldd2, ldc2, mode2, ldob, dupz2;
};

// tile 128x64, warp 32x32, 8 warps, 2-stage cp.async
// stage: A(128x40 fp16) | Bh(64x40) | Bl(64x40)
#define LDSE 40
#define A_T (128 * LDSE * 2)     // 10240
#define B_T (64 * LDSE * 2)      // 5120
#define STAGE_B (A_T + 2 * B_T)  // 20480
#define DYN_SMEM (2 * STAGE_B)   // 40960

__device__ __forceinline__ void gemm_body(const GJob& J, int xt, char* smc, uint32_t smb)
{
    const int tid  = threadIdx.x;
    const int wid  = tid >> 5;
    const int lane = tid & 31;

    const int row0   = blockIdx.y * 128;
    const int n0     = xt * 64;
    const int kslice = n0 >> 8;
    const int wc0    = n0 & 255;

    const __half* wBh1 = J.W1h + kslice * 65536;
    const __half* wBl1 = J.W1l + kslice * 65536;
    const __half* wBh2 = J.W2h ? J.W2h + kslice * 65536 : (const __half*)0;
    const __half* wBl2 = J.W2l ? J.W2l + kslice * 65536 : (const __half*)0;

    const int NCH = J.nPair * 8;

    const int lrowA = tid >> 1;
    const int lkofA = (tid & 1) * 16;
    const int lrowB = tid >> 2;
    const int lkofB = (tid & 3) * 8;

    float acc[32];
#pragma unroll
    for (int i = 0; i < 32; i++) acc[i] = 0.f;

    const int wm = (wid >> 1) * 32;
    const int wn = (wid & 1) * 32;

    auto load_chunk = [&](int c, int buf) {
        const __half *pA, *pWh, *pWl;
        int lda;
        if (c < 8) { pA = J.A1; lda = J.lda1; pWh = wBh1; pWl = wBl1; }
        else       { pA = J.A2; lda = J.lda2; pWh = wBh2; pWl = wBl2; }
        const int k0 = (c & 7) * 32;
        const uint32_t sb = smb + buf * STAGE_B;
        const uint32_t soA = (lrowA * LDSE + lkofA) * 2;
        const __half* gA = pA + (size_t)(row0 + lrowA) * lda + k0 + lkofA;
        CP16(sb + soA,      gA);
        CP16(sb + soA + 16, gA + 8);
        const uint32_t soB = (lrowB * LDSE + lkofB) * 2;
        CP16(sb + A_T + soB,       pWh + (size_t)(wc0 + lrowB) * 256 + k0 + lkofB);
        CP16(sb + A_T + B_T + soB, pWl + (size_t)(wc0 + lrowB) * 256 + k0 + lkofB);
        CP_COMMIT();
    };

    load_chunk(0, 0);

    const uint32_t aRow  = (uint32_t)(wm + (lane & 15));
    const uint32_t aKh   = (uint32_t)((lane >> 4) * 8);
    const uint32_t bRow2 = (uint32_t)(wn + (lane & 7) + ((lane >> 4) * 8));
    const uint32_t bKc   = (uint32_t)(((lane >> 3) & 1) * 8);

    for (int c = 0; c < NCH; c++) {
        if (c + 1 < NCH) { load_chunk(c + 1, (c + 1) & 1); CP_WAIT1(); }
        else             { CP_WAIT0(); }
        __syncthreads();

        const uint32_t sb = smb + (c & 1) * STAGE_B;
#pragma unroll
        for (int ks = 0; ks < 2; ks++) {
            uint32_t a[2][4];
#pragma unroll
            for (int i = 0; i < 2; i++)
                ldm_x4(a[i], sb + ((aRow + i * 16) * LDSE + ks * 16 + aKh) * 2);
#pragma unroll
            for (int jp = 0; jp < 2; jp++) {
                uint32_t bh4[4], bl4[4];
                const uint32_t boff = ((bRow2 + jp * 16) * LDSE + ks * 16 + bKc) * 2;
                ldm_x4(bh4, sb + A_T + boff);
                ldm_x4(bl4, sb + A_T + B_T + boff);
#pragma unroll
                for (int i = 0; i < 2; i++) {
                    float* d0 = &acc[(i * 4 + jp * 2) * 4];
                    float* d1 = &acc[(i * 4 + jp * 2 + 1) * 4];
                    mma_f16(d0, a[i], bh4);
                    mma_f16(d0, a[i], bl4);
                    mma_f16(d1, a[i], bh4 + 2);
                    mma_f16(d1, a[i], bl4 + 2);
                }
            }
        }
        __syncthreads();
    }

    // epilogue: regs -> smem (128 x 68 f32) -> gmem
    float* smf = (float*)smc;
    {
        const int r0 = lane >> 2;
        const int cc = (lane & 3) * 2;
#pragma unroll
        for (int i = 0; i < 2; i++)
#pragma unroll
            for (int j = 0; j < 4; j++) {
                const float* d = &acc[(i * 4 + j) * 4];
                const int rr = wm + i * 16 + r0;
                const int col = wn + j * 8 + cc;
                smf[rr * 68 + col]           = d[0];
                smf[rr * 68 + col + 1]       = d[1];
                smf[(rr + 8) * 68 + col]     = d[2];
                smf[(rr + 8) * 68 + col + 1] = d[3];
            }
    }
    __syncthreads();

    const bool c_vec  = ((((uintptr_t)J.C) & 15) == 0) && ((J.ldc & 3) == 0);
    const bool c2_vec = J.C2 && ((((uintptr_t)J.C2) & 15) == 0) && ((J.ldc2 & 3) == 0);

#pragma unroll
    for (int it = 0; it < 8; it++) {
        const int f4 = it * 256 + tid;
        const int rr = f4 >> 4;
        const int c4 = (f4 & 15) * 4;
        float4 v = *(float4*)&smf[rr * 68 + c4];
        const int row = row0 + rr;
        const int gn  = n0 + c4;
        float o[4];
        float dv[4] = {0.f, 0.f, 0.f, 0.f};
        if (J.mode == EPI_ADD || J.mode == EPI_MUL) {
            float4 d4 = *(const float4*)(J.Dop + (size_t)row * J.ldd + gn);
            dv[0] = d4.x; dv[1] = d4.y; dv[2] = d4.z; dv[3] = d4.w;
        }
#pragma unroll
        for (int q = 0; q < 4; q++) {
            const float val = (&v.x)[q];
            const float bv = J.bias ? J.bias[gn + q] : 0.f;
            float res;
            if (J.mode == EPI_SIG)      res = 1.f / (1.f + expf(-(val + bv)));
            else if (J.mode == EPI_ADD) res = val + dv[q] + bv;
            else if (J.mode == EPI_MUL) res = val * dv[q] + bv;
            else if (J.mode == EPI_OMZ) res = 1.f - (val + bv);
            else                        res = val + bv;
            o[q] = res;
        }
        float* cp = J.C + (size_t)row * J.ldc + gn;
        if (c_vec) *(float4*)cp = make_float4(o[0], o[1], o[2], o[3]);
        else { cp[0] = o[0]; cp[1] = o[1]; cp[2] = o[2]; cp[3] = o[3]; }

        if (J.dupz2 && gn < 256) {
            float* zp = J.C + (size_t)row * J.ldc + 512 + gn;
            zp[0] = o[0]; zp[1] = o[1]; zp[2] = o[2]; zp[3] = o[3];
        }

        if (J.C2) {
            float o2[4];
            float dv2[4] = {0.f, 0.f, 0.f, 0.f};
            if (J.mode2 == EPI_ADD || J.mode2 == EPI_MUL) {
                float4 d4 = *(const float4*)(J.D2op + (size_t)row * J.ldd2 + gn);
                dv2[0] = d4.x; dv2[1] = d4.y; dv2[2] = d4.z; dv2[3] = d4.w;
            }
#pragma unroll
            for (int q = 0; q < 4; q++) {
                const float val = (&v.x)[q];
                const float bv = J.bias ? J.bias[gn + q] : 0.f;
                float res;
                if (J.mode2 == EPI_SIG)      res = 1.f / (1.f + expf(-(val + bv)));
                else if (J.mode2 == EPI_ADD) res = val + dv2[q] + bv;
                else if (J.mode2 == EPI_MUL) res = val * dv2[q] + bv;
                else if (J.mode2 == EPI_OMZ) res = 1.f - (val + bv);
                else                         res = val + bv;
                o2[q] = res;
            }
            float* cp2 = J.C2 + (size_t)row * J.ldc2 + gn;
            if (c2_vec) *(float4*)cp2 = make_float4(o2[0], o2[1], o2[2], o2[3]);
            else { cp2[0] = o2[0]; cp2[1] = o2[1]; cp2[2] = o2[2]; cp2[3] = o2[3]; }
        }

        if (J.Ob) {
            __half2* ph = (__half2*)(J.Ob + (size_t)row * J.ldob + gn);
            ph[0] = __half2{__float2half(o[0]), __float2half(o[1])};
            ph[1] = __half2{__float2half(o[2]), __float2half(o[3])};
        }
    }
}

__global__ __launch_bounds__(256, 3)
void tc_gemm2(GJob j0, GJob j1, int nx0)
{
    extern __shared__ char smc[];
    const uint32_t smb = smem_u32(smc);
    if ((int)blockIdx.x < nx0) gemm_body(j0, blockIdx.x, smc, smb);
    else                       gemm_body(j1, blockIdx.x - nx0, smc, smb);
}

// ---------------- prep: weights transpose+split + input convert ----------
__global__ __launch_bounds__(256)
void prep_all(const float* __restrict__ L, const float* __restrict__ R,
              const float* __restrict__ x, const float* __restrict__ h,
              __half* __restrict__ Lh, __half* __restrict__ Ll,
              __half* __restrict__ Rh, __half* __restrict__ Rl,
              __half* __restrict__ xf, __half* __restrict__ hf)
{
    __shared__ float t[32][33];
    const int bid = blockIdx.x;
    if (bid < 512) {
        const int mz = bid >> 6;
        const int rem = bid & 63;
        const int h0 = (rem >> 3) * 32, d0 = (rem & 7) * 32;
        const float* src = (mz < 4) ? L : R;
        __half* dh = (mz < 4) ? Lh : Rh;
        __half* dl = (mz < 4) ? Ll : Rl;
        const int k = mz & 3;
        const int tx = threadIdx.x & 31, ty = threadIdx.x >> 5;
        for (int i = 0; i < 32; i += 8)
            t[ty + i][tx] = src[k * 65536 + (h0 + ty + i) * 256 + d0 + tx];
        __syncthreads();
        for (int i = 0; i < 32; i += 8) {
            const float v = t[tx][ty + i];
            const __half hi = __float2half_rn(v);
            const __half lo = __float2half_rn(v - __half2float(hi));
            dh[k * 65536 + (d0 + ty + i) * 256 + h0 + tx] = hi;
            dl[k * 65536 + (d0 + ty + i) * 256 + h0 + tx] = lo;
        }
    } else {
        const int i = (bid - 512) * 256 + threadIdx.x;
        const int n = BATCH * HID;
        if (i < n) xf[i] = __float2half_rn(x[i]);
        else       hf[i - n] = __float2half_rn(h[i - n]);
    }
}

// ---------------- mixture (multi-job) ----------------
struct MJob {
    const float *cand, *P, *Q;
    float *out1, *out2;
    __half *ob;
    float *rows;
    int ldcand, ldp, ldq, c3mode, ldo1;
};

__device__ __forceinline__ void mix_body(const MJob& M, int local,
                                         const float* __restrict__ b3,
                                         const float* __restrict__ Ws)
{
    const int warp = threadIdx.x >> 5;
    const int lane = threadIdx.x & 31;
    const int b = local * 8 + warp;

    const float* cr = M.cand + (size_t)b * M.ldcand;
    const float* pr = M.P + (size_t)b * M.ldp;
    const float* qr = M.Q ? M.Q + (size_t)b * M.ldq : (const float*)0;

    float c[2][4][4];
    float s0 = 0.f, s1 = 0.f, s2 = 0.f, s3 = 0.f;

#pragma unroll
    for (int g = 0; g < 2; g++) {
        const int j = g * 128 + lane * 4;
        float4 v0 = *(const float4*)(cr + j);
        float4 v1 = *(const float4*)(cr + 256 + j);
        float4 v2 = *(const float4*)(cr + 512 + j);
        float4 bw = *(const float4*)(b3 + j);
        float4 wv = *(const float4*)(Ws + j);
        float p0 = pr[j], p1 = pr[j + 1], p2 = pr[j + 2], p3 = pr[j + 3];
        float c3v[4];
        if (M.c3mode == C3_ADD) {
            c3v[0] = p0 + qr[j]     + bw.x;
            c3v[1] = p1 + qr[j + 1] + bw.y;
            c3v[2] = p2 + qr[j + 2] + bw.z;
            c3v[3] = p3 + qr[j + 3] + bw.w;
        } else if (M.c3mode == C3_OMZ) {
            c3v[0] = 1.f - (p0 + bw.x);
            c3v[1] = 1.f - (p1 + bw.y);
            c3v[2] = 1.f - (p2 + bw.z);
            c3v[3] = 1.f - (p3 + bw.w);
        } else {
            c3v[0] = p0 * qr[j]     + bw.x;
            c3v[1] = p1 * qr[j + 1] + bw.y;
            c3v[2] = p2 * qr[j + 2] + bw.z;
            c3v[3] = p3 * qr[j + 3] + bw.w;
        }
        c[g][0][0] = v0.x; c[g][0][1] = v0.y; c[g][0][2] = v0.z; c[g][0][3] = v0.w;
        c[g][1][0] = v1.x; c[g][1][1] = v1.y; c[g][1][2] = v1.z; c[g][1][3] = v1.w;
        c[g][2][0] = v2.x; c[g][2][1] = v2.y; c[g][2][2] = v2.z; c[g][2][3] = v2.w;
        c[g][3][0] = c3v[0]; c[g][3][1] = c3v[1]; c[g][3][2] = c3v[2]; c[g][3][3] = c3v[3];
        const float w0 = wv.x, w1 = wv.y, w2 = wv.z, w3 = wv.w;
        s0 += v0.x * w0 + v0.y * w1 + v0.z * w2 + v0.w * w3;
        s1 += v1.x * w0 + v1.y * w1 + v1.z * w2 + v1.w * w3;
        s2 += v2.x * w0 + v2.y * w1 + v2.z * w2 + v2.w * w3;
        s3 += c3v[0] * w0 + c3v[1] * w1 + c3v[2] * w2 + c3v[3] * w3;
    }

#pragma unroll
    for (int o = 16; o > 0; o >>= 1) {
        s0 += __shfl_xor_sync(0xffffffffu, s0, o);
        s1 += __shfl_xor_sync(0xffffffffu, s1, o);
        s2 += __shfl_xor_sync(0xffffffffu, s2, o);
        s3 += __shfl_xor_sync(0xffffffffu, s3, o);
    }

    if (lane < 4) {
        const float sv = (lane == 0) ? s0 : (lane == 1) ? s1 : (lane == 2) ? s2 : s3;
        M.rows[lane * BATCH + b] = sv;
    }

    const float mx = fmaxf(fmaxf(s0, s1), fmaxf(s2, s3));
    const float e0 = expf(s0 - mx), e1 = expf(s1 - mx);
    const float e2 = expf(s2 - mx), e3 = expf(s3 - mx);
    const float inv = 1.f / (e0 + e1 + e2 + e3);
    const float w0 = e0 * inv, w1 = e1 * inv, w2 = e2 * inv, w3 = e3 * inv;

#pragma unroll
    for (int g = 0; g < 2; g++) {
        const int j = g * 128 + lane * 4;
        float o[4];
#pragma unroll
        for (int q = 0; q < 4; q++)
            o[q] = w0 * c[g][0][q] + w1 * c[g][1][q] + w2 * c[g][2][q] + w3 * c[g][3][q];

        float* op = M.out1 + (size_t)b * M.ldo1 + j;
        op[0] = o[0]; op[1] = o[1]; op[2] = o[2]; op[3] = o[3];
        if (M.out2)
            *(float4*)(M.out2 + (size_t)b * HID + j) = make_float4(o[0], o[1], o[2], o[3]);
        if (M.ob) {
            __half2* ph = (__half2*)(M.ob + (size_t)b * HID + j);
            ph[0] = __half2{__float2half(o[0]), __float2half(o[1])};
            ph[1] = __half2{__float2half(o[2]), __float2half(o[3])};
        }
    }
}

__global__ __launch_bounds__(256)
void mix3(MJob m0, MJob m1, MJob m2, const float* b3, const float* Ws)
{
    const int jid = blockIdx.x >> 11;
    const int local = blockIdx.x & 2047;
    if (jid == 0)      mix_body(m0, local, b3, Ws);
    else if (jid == 1) mix_body(m1, local, b3, Ws);
    else               mix_body(m2, local, b3, Ws);
}

// ---------------- finalize ----------------
__global__ __launch_bounds__(256)
void fin_sum(const float* __restrict__ rs)
{
    __shared__ double tmp[256];
    const int idx = blockIdx.x;
    const int tid = threadIdx.x;
    double p = 0.0;
    for (int i = tid; i < BATCH; i += 256) p += (double)rs[idx * BATCH + i];
    tmp[tid] = p;
    __syncthreads();
    for (int o = 128; o > 0; o >>= 1) {
        if (tid < o) tmp[tid] += tmp[tid + o];
        __syncthreads();
    }
    if (tid == 0) g_ssum[idx] = tmp[0];
}

__global__ void fin_out(float* __restrict__ out)
{
    if (threadIdx.x == 0) {
        out[OFF_GS + 0] = 0.f;
        out[OFF_GS + 1] = 1.f;
        out[OFF_GS + 2] = 0.f;
        for (int s = 0; s < 6; s++) {
            double best = g_ssum[s * 4]; int bi = 0;
            for (int k = 1; k < 4; k++)
                if (g_ssum[s * 4 + k] > best) { best = g_ssum[s * 4 + k]; bi = k; }
            double second = -1e300;
            for (int k = 0; k < 4; k++)
                if (k != bi && g_ssum[s * 4 + k] > second) second = g_ssum[s * 4 + k];
            out[OFF_GS + 3 + s] = (float)bi;
            out[OFF_MARG + s]   = (float)(best - second);
        }
    }
}

// ---------------- launcher ----------------
extern "C" void kernel_launch(void* const* d_in, const int* in_sizes, int n_in,
                              void* d_out, int out_size)
{
    const float* x  = (const float*)d_in[0];
    const float* h  = (const float*)d_in[1];
    const float* L  = (const float*)d_in[2];
    const float* R  = (const float*)d_in[3];
    const float* bb = (const float*)d_in[4];
    const float* Ws = (const float*)d_in[5];
    float* out = (float*)d_out;

    static bool attr_done = false;
    if (!attr_done) {
        cudaFuncSetAttribute(tc_gemm2, cudaFuncAttributeMaxDynamicSharedMemorySize, DYN_SMEM);
        attr_done = true;
    }

    float *p_hL, *p_tmp, *p_cand, *p_cand2, *p_rows;
    __half *p_hf, *p_w;
    cudaGetSymbolAddress((void**)&p_hL,    g_hL);
    cudaGetSymbolAddress((void**)&p_tmp,   g_tmp);
    cudaGetSymbolAddress((void**)&p_cand,  g_cand);
    cudaGetSymbolAddress((void**)&p_cand2, g_cand2);
    cudaGetSymbolAddress((void**)&p_rows,  g_rows);
    cudaGetSymbolAddress((void**)&p_hf,    g_hf);
    cudaGetSymbolAddress((void**)&p_w,     g_wh);

    __half* xf   = p_hf + 0ull * UNIT;
    __half* hf   = p_hf + 1ull * UNIT;
    __half* z1r  = p_hf + 2ull * UNIT;   // 2 units, ld 512
    __half* rh   = p_hf + 4ull * UNIT;
    __half* ht   = p_hf + 5ull * UNIT;
    __half* om   = p_hf + 6ull * UNIT;
    __half* zt   = p_hf + 7ull * UNIT;
    __half* z2h  = p_hf + 8ull * UNIT;

    __half* Lh = p_w + 0ull * WUNIT;
    __half* Ll = p_w + 1ull * WUNIT;
    __half* Rh = p_w + 2ull * WUNIT;
    __half* Rl = p_w + 3ull * WUNIT;

    float* gnode = out + OFF_GNODE;
    const float* b3 = bb + 768;
    const dim3 blk(256);

    prep_all<<<512 + 2 * UNIT / 256, blk>>>(L, R, x, h, Lh, Ll, Rh, Rl, xf, hf);

    // ---- GEMM jobs
    GJob jS0{}; // [z1|r] = sig(x@L + h@R + b), N=512
    jS0.A1 = xf; jS0.lda1 = 256; jS0.W1h = Lh; jS0.W1l = Ll;
    jS0.A2 = hf; jS0.lda2 = 256; jS0.W2h = Rh; jS0.W2l = Rl;
    jS0.nPair = 2; jS0.bias = bb;
    jS0.C = gnode; jS0.ldc = GROW; jS0.mode = EPI_SIG;
    jS0.Ob = z1r; jS0.ldob = 512; jS0.dupz2 = 1;

    GJob jHL{}; // hL = h @ L[0..2]
    jHL.A1 = hf; jHL.lda1 = 256; jHL.W1h = Lh; jHL.W1l = Ll;
    jHL.nPair = 1;
    jHL.C = p_hL; jHL.ldc = 768; jHL.mode = EPI_NONE;

    GJob jCE{}; // v = z1@R; cand_C = 1-(v+b) ; cand_E = v*hL + b
    jCE.A1 = z1r; jCE.lda1 = 512; jCE.W1h = Rh; jCE.W1l = Rl;
    jCE.nPair = 1; jCE.bias = bb;
    jCE.C = p_cand; jCE.ldc = 768; jCE.mode = EPI_OMZ;
    jCE.D2op = p_hL; jCE.ldd2 = 768; jCE.C2 = p_tmp; jCE.ldc2 = 768; jCE.mode2 = EPI_MUL;

    GJob jA{};  // cand_A = r@R + hL + b
    jA.A1 = z1r + 256; jA.lda1 = 512; jA.W1h = Rh; jA.W1l = Rl;
    jA.nPair = 1; jA.bias = bb;
    jA.Dop = p_hL; jA.ldd = 768;
    jA.C = p_cand2; jA.ldc = 768; jA.mode = EPI_ADD;

    GJob jB{};  // cand_B = x@L + rh@R + b
    jB.A1 = xf; jB.lda1 = 256; jB.W1h = Lh; jB.W1l = Ll;
    jB.A2 = rh; jB.lda2 = 256; jB.W2h = Rh; jB.W2l = Rl;
    jB.nPair = 2; jB.bias = bb;
    jB.C = p_cand; jB.ldc = 768; jB.mode = EPI_NONE;

    GJob jOR{}; // omzR = omz@R
    jOR.A1 = om; jOR.lda1 = 256; jOR.W1h = Rh; jOR.W1l = Rl;
    jOR.nPair = 1;
    jOR.C = p_tmp; jOR.ldc = 768; jOR.mode = EPI_NONE;

    GJob jD{};  // cand_D = (ht@L) * omzR + b
    jD.A1 = ht; jD.lda1 = 256; jD.W1h = Lh; jD.W1l = Ll;
    jD.nPair = 1; jD.bias = bb;
    jD.Dop = p_tmp; jD.ldd = 768;
    jD.C = p_cand2; jD.ldc = 768; jD.mode = EPI_MUL;

    GJob jF{};  // cand_F = zt@L + z2h@R + b
    jF.A1 = zt; jF.lda1 = 256; jF.W1h = Lh; jF.W1l = Ll;
    jF.A2 = z2h; jF.lda2 = 256; jF.W2h = Rh; jF.W2l = Rl;
    jF.nPair = 2; jF.bias = bb;
    jF.C = p_cand; jF.ldc = 768; jF.mode = EPI_NONE;

    // ---- mix jobs
    MJob mC{}; mC.cand = p_cand; mC.ldcand = 768; mC.P = gnode; mC.ldp = GROW;
    mC.c3mode = C3_OMZ; mC.out1 = gnode + 5 * HID; mC.ldo1 = GROW;
    mC.ob = om; mC.rows = p_rows + 2 * 4 * BATCH;

    MJob mE{}; mE.cand = p_tmp; mE.ldcand = 768; mE.P = h; mE.ldp = HID;
    mE.Q = gnode; mE.ldq = GROW; mE.c3mode = C3_MUL;
    mE.out1 = gnode + 7 * HID; mE.ldo1 = GROW;
    mE.ob = z2h; mE.rows = p_rows + 4 * 4 * BATCH;

    MJob mA{}; mA.cand = p_cand2; mA.ldcand = 768; mA.P = h; mA.ldp = HID;
    mA.Q = gnode + 1 * HID; mA.ldq = GROW; mA.c3mode = C3_ADD;
    mA.out1 = gnode + 3 * HID; mA.ldo1 = GROW;
    mA.ob = rh; mA.rows = p_rows + 0 * 4 * BATCH;

    MJob mB{}; mB.cand = p_cand; mB.ldcand = 768; mB.P = x; mB.ldp = HID;
    mB.Q = gnode + 3 * HID; mB.ldq = GROW; mB.c3mode = C3_ADD;
    mB.out1 = gnode + 4 * HID; mB.ldo1 = GROW;
    mB.ob = ht; mB.rows = p_rows + 1 * 4 * BATCH;

    MJob mD{}; mD.cand = p_cand2; mD.ldcand = 768; mD.P = gnode + 4 * HID; mD.ldp = GROW;
    mD.Q = gnode + 5 * HID; mD.ldq = GROW; mD.c3mode = C3_MUL;
    mD.out1 = gnode + 6 * HID; mD.ldo1 = GROW;
    mD.ob = zt; mD.rows = p_rows + 3 * 4 * BATCH;

    MJob mF{}; mF.cand = p_cand; mF.ldcand = 768; mF.P = gnode + 6 * HID; mF.ldp = GROW;
    mF.Q = gnode + 7 * HID; mF.ldq = GROW; mF.c3mode = C3_ADD;
    mF.out1 = gnode + 8 * HID; mF.ldo1 = GROW; mF.out2 = out + OFF_HNEXT;
    mF.rows = p_rows + 5 * 4 * BATCH;

    // wave 1: stage0 (8 tiles) + hL (12 tiles)
    tc_gemm2<<<dim3(20, BATCH / 128), blk, DYN_SMEM>>>(jS0, jHL, 8);
    // wave 2: CE (12) + A (12)
    tc_gemm2<<<dim3(24, BATCH / 128), blk, DYN_SMEM>>>(jCE, jA, 12);
    // wave 3: mix C, E, A
    mix3<<<3 * 2048, blk>>>(mC, mE, mA, b3, Ws);
    // wave 4: B (12) + omzR (12)
    tc_gemm2<<<dim3(24, BATCH / 128), blk, DYN_SMEM>>>(jB, jOR, 12);
    // wave 5: mix B
    mix3<<<2048, blk>>>(mB, mB, mB, b3, Ws);
    // wave 6: D
    tc_gemm2<<<dim3(12, BATCH / 128), blk, DYN_SMEM>>>(jD, jD, 12);
    // wave 7: mix D
    mix3<<<2048, blk>>>(mD, mD, mD, b3, Ws);
    // wave 8: F
    tc_gemm2<<<dim3(12, BATCH / 128), blk, DYN_SMEM>>>(jF, jF, 12);
    // wave 9: mix F
    mix3<<<2048, blk>>>(mF, mF, mF, b3, Ws);

    fin_sum<<<24, blk>>>(p_rows);
    fin_out<<<1, 32>>>(out);
}